// round 6
// baseline (speedup 1.0000x reference)
#include <cuda_runtime.h>

#define NN 20000
#define FF 256
#define RR 8
#define HH 4
#define UU 64
#define BB 4
#define CC 32   // R*H
#define EE 320000
#define NBLK 79  // ceil(NN/256)

typedef unsigned long long ull;

// ---------------- f32x2 packed math helpers ----------------
__device__ __forceinline__ ull splat2(float v) {
    ull r; asm("mov.b64 %0, {%1, %1};" : "=l"(r) : "f"(v)); return r;
}
__device__ __forceinline__ ull pack2(float lo, float hi) {
    ull r; asm("mov.b64 %0, {%1, %2};" : "=l"(r) : "f"(lo), "f"(hi)); return r;
}
__device__ __forceinline__ void fma2(ull& d, ull a, ull b) {
    asm("fma.rn.f32x2 %0, %1, %2, %0;" : "+l"(d) : "l"(a), "l"(b));
}
__device__ __forceinline__ ull mul2(ull a, ull b) {
    ull d; asm("mul.rn.f32x2 %0, %1, %2;" : "=l"(d) : "l"(a), "l"(b)); return d;
}
__device__ __forceinline__ void unpk2(float& lo, float& hi, ull v) {
    asm("mov.b64 {%0, %1}, %2;" : "=f"(lo), "=f"(hi) : "l"(v));
}

// ---------------- device scratch ----------------
__device__ float  g_y[NN * BB * UU];   // y[n][u*4 + b]  (interleaved, 20.48 MB)
__device__ float  g_qk[NN * 64];       // [n][c] c<32: q(c=r*4+h), c>=32: k
__device__ float  g_wqk[FF * 64];      // [f][c] k-major weight for qk GEMM
__device__ int    g_deg[NN];           // zero at init; re-zeroed by k_scan each call
__device__ int    g_off[NN + 1];
__device__ int    g_cur[NN];
__device__ int    g_bsum[NBLK];        // 0 = not ready; -(sum+1) = ready. reset by k_scatter
__device__ int    g_packed[EE];        // src | (rel<<16), CSR-sorted by dst

// ---------------- static stream/event bootstrap ----------------
static cudaStream_t s_s1 = 0, s_s2 = 0;
static cudaEvent_t  s_evRoot = 0, s_evMisc = 0, s_evA = 0, s_evB = 0;
static bool s_forkOK = false;
namespace {
struct Boot {
    Boot() {
        bool ok = true;
        ok &= (cudaStreamCreateWithFlags(&s_s1, cudaStreamNonBlocking) == cudaSuccess);
        ok &= (cudaStreamCreateWithFlags(&s_s2, cudaStreamNonBlocking) == cudaSuccess);
        ok &= (cudaEventCreateWithFlags(&s_evRoot, cudaEventDisableTiming) == cudaSuccess);
        ok &= (cudaEventCreateWithFlags(&s_evMisc, cudaEventDisableTiming) == cudaSuccess);
        ok &= (cudaEventCreateWithFlags(&s_evA, cudaEventDisableTiming) == cudaSuccess);
        ok &= (cudaEventCreateWithFlags(&s_evB, cudaEventDisableTiming) == cudaSuccess);
        s_forkOK = ok;
    }
} s_boot;
}

// ---------------- K0: prep (blocks 0..31) + hist (blocks 32..344) ----------
#define HBLK ((EE / 4 + 255) / 256)   // 313
__global__ void k_misc(const float* __restrict__ coeff,
                       const float* __restrict__ basis,
                       const float* __restrict__ aq,
                       const float* __restrict__ ak,
                       const int* __restrict__ dst) {
    int bid = blockIdx.x, t = threadIdx.x;
    if (bid < 32) {
        // ---- qk weight build: wqk[f][c] ----
        int idx = bid * 256 + t;      // < 8192 = CC*FF exactly
        int c = idx >> 8;
        int f = idx & 255;
        float sq = 0.f, sk = 0.f;
#pragma unroll
        for (int b = 0; b < BB; ++b) {
            const float* bp = basis + (b * FF + f) * UU;
            const float* aqc = aq + c * UU;
            const float* akc = ak + c * UU;
            float dq = 0.f, dk = 0.f;
#pragma unroll 8
            for (int u = 0; u < UU; ++u) {
                float bv = bp[u];
                dq += bv * aqc[u];
                dk += bv * akc[u];
            }
            float cb = coeff[c * BB + b];
            sq += cb * dq;
            sk += cb * dk;
        }
        g_wqk[f * 64 + c]      = sq;
        g_wqk[f * 64 + 32 + c] = sk;
    } else {
        // ---- degree histogram ----
        int j = (bid - 32) * 256 + t;
        if (j < EE / 4) {
            int4 d4 = ((const int4*)dst)[j];
            atomicAdd(&g_deg[d4.x], 1);
            atomicAdd(&g_deg[d4.y], 1);
            atomicAdd(&g_deg[d4.z], 1);
            atomicAdd(&g_deg[d4.w], 1);
        }
    }
}

// ---------------- K1: generic 128x64 FFMA2 GEMM ----------------
#define GROWS 128
#define KC 128
#define XPAD 132
#define GEMM_SMEM ((KC * XPAD + KC * 64) * 4)

__global__ __launch_bounds__(256, 2) void k_gemm(const float* __restrict__ x,
                                                 const float* __restrict__ w,
                                                 float* __restrict__ out,
                                                 int ostride, int cmul, int cadd0,
                                                 int bstride, int caddstep) {
    extern __shared__ float sm[];
    float* xs = sm;                 // [KC][XPAD] transposed x chunk
    float* ws = sm + KC * XPAD;     // [KC][64]
    int tid = threadIdx.x;
    int tx = tid & 15, ty = tid >> 4;
    int m0 = blockIdx.x * GROWS;
    const float* wb = w + (size_t)blockIdx.y * bstride;
    int cadd = cadd0 + blockIdx.y * caddstep;

    ull acc[4][4];
#pragma unroll
    for (int i = 0; i < 4; ++i)
#pragma unroll
        for (int j = 0; j < 4; ++j) acc[i][j] = 0ull;

    for (int kc = 0; kc < 2; ++kc) {
        if (kc) __syncthreads();
        const float4* w4 = (const float4*)(wb + kc * KC * 64);
        float4* ws4 = (float4*)ws;
        for (int i = tid; i < KC * 16; i += 256) ws4[i] = w4[i];
        const float4* x4 = (const float4*)x;
        for (int i = tid; i < GROWS * 32; i += 256) {
            int row = i >> 5, k4 = i & 31;
            int n = m0 + row;
            float4 v = make_float4(0.f, 0.f, 0.f, 0.f);
            if (n < NN) v = x4[n * 64 + kc * 32 + k4];
            xs[(k4 * 4 + 0) * XPAD + row] = v.x;
            xs[(k4 * 4 + 1) * XPAD + row] = v.y;
            xs[(k4 * 4 + 2) * XPAD + row] = v.z;
            xs[(k4 * 4 + 3) * XPAD + row] = v.w;
        }
        __syncthreads();

        const float* wp = ws + tx * 4;
        const float* xp = xs + ty * 8;
#pragma unroll 8
        for (int k = 0; k < KC; ++k) {
            float4 bv = *(const float4*)(wp + k * 64);
            const float* xr = xp + k * XPAD;
            ull a0 = *(const ull*)(xr);
            ull a1 = *(const ull*)(xr + 2);
            ull a2 = *(const ull*)(xr + 4);
            ull a3 = *(const ull*)(xr + 6);
            ull s0 = splat2(bv.x), s1 = splat2(bv.y),
                s2 = splat2(bv.z), s3 = splat2(bv.w);
            fma2(acc[0][0], a0, s0); fma2(acc[1][0], a1, s0);
            fma2(acc[2][0], a2, s0); fma2(acc[3][0], a3, s0);
            fma2(acc[0][1], a0, s1); fma2(acc[1][1], a1, s1);
            fma2(acc[2][1], a2, s1); fma2(acc[3][1], a3, s1);
            fma2(acc[0][2], a0, s2); fma2(acc[1][2], a1, s2);
            fma2(acc[2][2], a2, s2); fma2(acc[3][2], a3, s2);
            fma2(acc[0][3], a0, s3); fma2(acc[1][3], a1, s3);
            fma2(acc[2][3], a2, s3); fma2(acc[3][3], a3, s3);
        }
    }

    int col0 = tx * 4;
#pragma unroll
    for (int ip = 0; ip < 4; ++ip) {
        float lo[4], hi[4];
#pragma unroll
        for (int j = 0; j < 4; ++j) unpk2(lo[j], hi[j], acc[ip][j]);
        int n0 = m0 + ty * 8 + ip * 2;
        if (n0 < NN) {
            float* o = out + (size_t)n0 * ostride + cadd;
#pragma unroll
            for (int j = 0; j < 4; ++j) o[(col0 + j) * cmul] = lo[j];
        }
        if (n0 + 1 < NN) {
            float* o = out + (size_t)(n0 + 1) * ostride + cadd;
#pragma unroll
            for (int j = 0; j < 4; ++j) o[(col0 + j) * cmul] = hi[j];
        }
    }
}

// ---------------- K2: single-pass scan with sentinel lookback ----------------
__global__ __launch_bounds__(256) void k_scan() {
    int t = threadIdx.x, lane = t & 31, wid = t >> 5, bid = blockIdx.x;
    int i = bid * 256 + t;
    int v = (i < NN) ? g_deg[i] : 0;
    int inc = v;
#pragma unroll
    for (int o = 1; o < 32; o <<= 1) {
        int u = __shfl_up_sync(0xffffffffu, inc, o);
        if (lane >= o) inc += u;
    }
    __shared__ int ws[8], ws2[8], s_base;
    if (lane == 31) ws[wid] = inc;
    __syncthreads();
    if (t == 0) {
        int btot = 0;
#pragma unroll
        for (int w = 0; w < 8; ++w) btot += ws[w];
        atomicExch(&g_bsum[bid], -(btot + 1));
    }
    int part = 0;
    if (t < bid) {
        volatile int* vb = g_bsum;
        int sv;
        do { sv = vb[t]; } while (sv >= 0);
        part = -sv - 1;
    }
#pragma unroll
    for (int o = 16; o; o >>= 1) part += __shfl_xor_sync(0xffffffffu, part, o);
    if (lane == 0) ws2[wid] = part;
    __syncthreads();
    if (t == 0) {
        int b = 0;
#pragma unroll
        for (int w = 0; w < 8; ++w) b += ws2[w];
        s_base = b;
    }
    __syncthreads();
    int wpre = 0;
#pragma unroll
    for (int w = 0; w < 8; ++w) wpre += (w < wid) ? ws[w] : 0;
    int excl = s_base + wpre + inc - v;
    if (i < NN) { g_off[i] = excl; g_cur[i] = excl; g_deg[i] = 0; }
    if (bid == NBLK - 1 && t == 255) g_off[NN] = EE;
}

// ---------------- K3: scatter (packed), x4 vectorized + g_bsum reset -------
__global__ void k_scatter(const int* __restrict__ src,
                          const int* __restrict__ dst,
                          const int* __restrict__ rel) {
    int j = blockIdx.x * blockDim.x + threadIdx.x;
    if (j < EE / 4) {
        int4 s4 = ((const int4*)src)[j];
        int4 d4 = ((const int4*)dst)[j];
        int4 r4 = ((const int4*)rel)[j];
        int p;
        p = atomicAdd(&g_cur[d4.x], 1); g_packed[p] = s4.x | (r4.x << 16);
        p = atomicAdd(&g_cur[d4.y], 1); g_packed[p] = s4.y | (r4.y << 16);
        p = atomicAdd(&g_cur[d4.z], 1); g_packed[p] = s4.z | (r4.z << 16);
        p = atomicAdd(&g_cur[d4.w], 1); g_packed[p] = s4.w | (r4.w << 16);
    }
    if (blockIdx.x == 0 && threadIdx.x < NBLK) g_bsum[threadIdx.x] = 0;
}

// ---------------- K4: fused online-softmax aggregation (round-4 body,
//                       y-loads hoisted ahead of the exp chain) ----------
__global__ __launch_bounds__(256, 6) void k_agg(const float* __restrict__ coeff,
                                                float* __restrict__ out) {
    __shared__ __align__(16) float cf[CC * BB];  // cf[(r*4+h)*4 + b]
    int tid = threadIdx.x;
    if (tid < CC * BB) cf[tid] = coeff[tid];
    __syncthreads();

    int lane = tid & 31, w = tid >> 5;
    int n = blockIdx.x * 8 + w;
    if (n >= NN) return;

    int beg = g_off[n], end = g_off[n + 1];
    if (beg == end) {
        out[n * UU + lane] = 0.f;
        out[n * UU + 32 + lane] = 0.f;
        return;
    }

    const float* kn = g_qk + n * 64 + 32;

    ull acc[4][2][2];  // [head][u-half][b-pair]
#pragma unroll
    for (int a = 0; a < 4; ++a)
#pragma unroll
        for (int hf = 0; hf < 2; ++hf) { acc[a][hf][0] = 0ull; acc[a][hf][1] = 0ull; }

    float mx[4], dn[4];
#pragma unroll
    for (int a = 0; a < 4; ++a) { mx[a] = __int_as_float(0xff800000); dn[a] = 0.f; }

    int pk = g_packed[beg];

    for (int e = beg; e < end; ++e) {
        int pkc = pk;
        if (e + 1 < end) pk = g_packed[e + 1];

        int s = pkc & 0xFFFF, r = pkc >> 16;
        // issue ALL memory for this edge up front (y overlaps the exp chain)
        const float4* yr = (const float4*)(g_y + (size_t)s * 256);
        float4 y0 = yr[lane];        // u = lane,    b0..b3
        float4 y1 = yr[32 + lane];   // u = lane+32, b0..b3
        float4 q  = *(const float4*)(g_qk + s * 64 + r * 4);
        float4 kk = *(const float4*)(kn + r * 4);

        float l[4];
        l[0] = q.x + kk.x; l[0] = l[0] > 0.f ? l[0] : 0.01f * l[0];
        l[1] = q.y + kk.y; l[1] = l[1] > 0.f ? l[1] : 0.01f * l[1];
        l[2] = q.z + kk.z; l[2] = l[2] > 0.f ? l[2] : 0.01f * l[2];
        l[3] = q.w + kk.w; l[3] = l[3] > 0.f ? l[3] : 0.01f * l[3];

        bool resc = false;
        float nmx[4];
#pragma unroll
        for (int a = 0; a < 4; ++a) {
            nmx[a] = fmaxf(mx[a], l[a]);
            resc |= (nmx[a] != mx[a]);
        }
        if (resc) {  // warp-uniform branch (l is uniform across lanes)
#pragma unroll
            for (int a = 0; a < 4; ++a) {
                float sc = __expf(mx[a] - nmx[a]);  // exp(-inf)=0 on first edge
                dn[a] *= sc;
                ull sc2 = splat2(sc);
                acc[a][0][0] = mul2(acc[a][0][0], sc2);
                acc[a][0][1] = mul2(acc[a][0][1], sc2);
                acc[a][1][0] = mul2(acc[a][1][0], sc2);
                acc[a][1][1] = mul2(acc[a][1][1], sc2);
                mx[a] = nmx[a];
            }
        }

        float wv[4];
#pragma unroll
        for (int a = 0; a < 4; ++a) {
            wv[a] = __expf(l[a] - mx[a]);
            dn[a] += wv[a];
        }

        ull y00 = pack2(y0.x, y0.y), y01 = pack2(y0.z, y0.w);
        ull y10 = pack2(y1.x, y1.y), y11 = pack2(y1.z, y1.w);
        const ull* cr = (const ull*)(cf + r * 16);
#pragma unroll
        for (int a = 0; a < 4; ++a) {
            ull wa = splat2(wv[a]);
            ull c0 = mul2(wa, cr[a * 2]);
            ull c1 = mul2(wa, cr[a * 2 + 1]);
            fma2(acc[a][0][0], c0, y00);
            fma2(acc[a][0][1], c1, y01);
            fma2(acc[a][1][0], c0, y10);
            fma2(acc[a][1][1], c1, y11);
        }
    }

    float o0 = 0.f, o1 = 0.f;
#pragma unroll
    for (int a = 0; a < 4; ++a) {
        float inv = 1.f / fmaxf(dn[a], 1e-16f);
        float l0, h0, l1, h1, l2, h2, l3, h3;
        unpk2(l0, h0, acc[a][0][0]);
        unpk2(l1, h1, acc[a][0][1]);
        unpk2(l2, h2, acc[a][1][0]);
        unpk2(l3, h3, acc[a][1][1]);
        o0 += inv * ((l0 + h0) + (l1 + h1));
        o1 += inv * ((l2 + h2) + (l3 + h3));
    }
    out[n * UU + lane] = 0.25f * o0;
    out[n * UU + 32 + lane] = 0.25f * o1;
}

// ---------------- launch ----------------
extern "C" void kernel_launch(void* const* d_in, const int* in_sizes, int n_in,
                              void* d_out, int out_size) {
    const float* x     = (const float*)d_in[0];
    const float* basis = (const float*)d_in[1];
    const float* coeff = (const float*)d_in[2];
    const float* aq    = (const float*)d_in[3];
    const float* ak    = (const float*)d_in[4];
    const int*   src   = (const int*)d_in[5];
    const int*   dst   = (const int*)d_in[6];
    const int*   rel   = (const int*)d_in[7];
    float* out = (float*)d_out;

    float* d_y;   cudaGetSymbolAddress((void**)&d_y, g_y);
    float* d_qk;  cudaGetSymbolAddress((void**)&d_qk, g_qk);
    float* d_wqk; cudaGetSymbolAddress((void**)&d_wqk, g_wqk);

    cudaFuncSetAttribute(k_gemm, cudaFuncAttributeMaxDynamicSharedMemorySize, GEMM_SMEM);

    cudaStream_t s1 = 0, s2 = 0;
    bool fork = s_forkOK;
    if (fork) {
        s1 = s_s1; s2 = s_s2;
        cudaEventRecord(s_evRoot, 0);
        cudaStreamWaitEvent(s1, s_evRoot, 0);
        cudaStreamWaitEvent(s2, s_evRoot, 0);
    }

    // --- side stream 2: y GEMM (independent of everything else) ---
    k_gemm<<<dim3((NN + GROWS - 1) / GROWS, BB), 256, GEMM_SMEM, s2>>>(
        x, basis, d_y, 256, 4, 0, FF * UU, 1);

    // --- main stream: prep + hist fused ---
    k_misc<<<32 + HBLK, 256>>>(coeff, basis, aq, ak, dst);
    if (fork) {
        cudaEventRecord(s_evMisc, 0);
        cudaStreamWaitEvent(s1, s_evMisc, 0);
    }

    // --- side stream 1: qk GEMM (needs g_wqk from misc) ---
    k_gemm<<<dim3((NN + GROWS - 1) / GROWS, 1), 256, GEMM_SMEM, s1>>>(
        x, d_wqk, d_qk, 64, 1, 0, 0, 0);

    if (fork) {
        cudaEventRecord(s_evA, s1);
        cudaEventRecord(s_evB, s2);
    }

    // --- main stream: scan + scatter ---
    k_scan<<<NBLK, 256>>>();
    k_scatter<<<(EE / 4 + 255) / 256, 256>>>(src, dst, rel);

    if (fork) {
        cudaStreamWaitEvent(0, s_evA, 0);
        cudaStreamWaitEvent(0, s_evB, 0);
    }
    k_agg<<<(NN + 7) / 8, 256>>>(coeff, out);
}

// round 7
// speedup vs baseline: 2.1620x; 2.1620x over previous
#include <cuda_runtime.h>

#define NN 20000
#define FF 256
#define RR 8
#define HH 4
#define UU 64
#define BB 4
#define CC 32   // R*H
#define EE 320000
#define NBLK 79  // ceil(NN/256)

typedef unsigned long long ull;

// ---------------- f32x2 packed math helpers ----------------
__device__ __forceinline__ ull splat2(float v) {
    ull r; asm("mov.b64 %0, {%1, %1};" : "=l"(r) : "f"(v)); return r;
}
__device__ __forceinline__ ull pack2(float lo, float hi) {
    ull r; asm("mov.b64 %0, {%1, %2};" : "=l"(r) : "f"(lo), "f"(hi)); return r;
}
__device__ __forceinline__ void fma2(ull& d, ull a, ull b) {
    asm("fma.rn.f32x2 %0, %1, %2, %0;" : "+l"(d) : "l"(a), "l"(b));
}
__device__ __forceinline__ ull mul2(ull a, ull b) {
    ull d; asm("mul.rn.f32x2 %0, %1, %2;" : "=l"(d) : "l"(a), "l"(b)); return d;
}
__device__ __forceinline__ void unpk2(float& lo, float& hi, ull v) {
    asm("mov.b64 {%0, %1}, %2;" : "=f"(lo), "=f"(hi) : "l"(v));
}

// ---------------- device scratch ----------------
__device__ float  g_y[NN * BB * UU];   // y[n][u*4 + b]  (interleaved, 20.48 MB)
__device__ float  g_qk[NN * 64];       // [n][c] c<32: q(c=r*4+h), c>=32: k
__device__ float  g_wqk[FF * 64];      // [f][c] k-major weight for qk GEMM
__device__ int    g_deg[NN];           // zero at init; re-zeroed by k_scan each call
__device__ int    g_off[NN + 1];
__device__ int    g_cur[NN];
__device__ int    g_bsum[NBLK];        // 0 = not ready; -(sum+1) = ready. reset by k_scatter
__device__ int    g_packed[EE];        // src | (rel<<16), CSR-sorted by dst

// ---------------- static stream/event bootstrap ----------------
static cudaStream_t s_s1 = 0, s_s2 = 0;
static cudaEvent_t  s_evRoot = 0, s_evMisc = 0, s_evA = 0, s_evB = 0;
static bool s_forkOK = false;
namespace {
struct Boot {
    Boot() {
        bool ok = true;
        ok &= (cudaStreamCreateWithFlags(&s_s1, cudaStreamNonBlocking) == cudaSuccess);
        ok &= (cudaStreamCreateWithFlags(&s_s2, cudaStreamNonBlocking) == cudaSuccess);
        ok &= (cudaEventCreateWithFlags(&s_evRoot, cudaEventDisableTiming) == cudaSuccess);
        ok &= (cudaEventCreateWithFlags(&s_evMisc, cudaEventDisableTiming) == cudaSuccess);
        ok &= (cudaEventCreateWithFlags(&s_evA, cudaEventDisableTiming) == cudaSuccess);
        ok &= (cudaEventCreateWithFlags(&s_evB, cudaEventDisableTiming) == cudaSuccess);
        s_forkOK = ok;
    }
} s_boot;
}

// ---------------- K0: prep (blocks 0..31) + hist (blocks 32..344) ----------
#define HBLK ((EE / 4 + 255) / 256)   // 313
__global__ void k_misc(const float* __restrict__ coeff,
                       const float* __restrict__ basis,
                       const float* __restrict__ aq,
                       const float* __restrict__ ak,
                       const int* __restrict__ dst) {
    int bid = blockIdx.x, t = threadIdx.x;
    if (bid < 32) {
        // ---- qk weight build: wqk[f][c] ----
        int idx = bid * 256 + t;      // < 8192 = CC*FF exactly
        int c = idx >> 8;
        int f = idx & 255;
        float sq = 0.f, sk = 0.f;
#pragma unroll
        for (int b = 0; b < BB; ++b) {
            const float* bp = basis + (b * FF + f) * UU;
            const float* aqc = aq + c * UU;
            const float* akc = ak + c * UU;
            float dq = 0.f, dk = 0.f;
#pragma unroll 8
            for (int u = 0; u < UU; ++u) {
                float bv = bp[u];
                dq += bv * aqc[u];
                dk += bv * akc[u];
            }
            float cb = coeff[c * BB + b];
            sq += cb * dq;
            sk += cb * dk;
        }
        g_wqk[f * 64 + c]      = sq;
        g_wqk[f * 64 + 32 + c] = sk;
    } else {
        // ---- degree histogram ----
        int j = (bid - 32) * 256 + t;
        if (j < EE / 4) {
            int4 d4 = ((const int4*)dst)[j];
            atomicAdd(&g_deg[d4.x], 1);
            atomicAdd(&g_deg[d4.y], 1);
            atomicAdd(&g_deg[d4.z], 1);
            atomicAdd(&g_deg[d4.w], 1);
        }
    }
}

// ---------------- K1: generic 128x64 FFMA2 GEMM ----------------
#define GROWS 128
#define KC 128
#define XPAD 132
#define GEMM_SMEM ((KC * XPAD + KC * 64) * 4)

__global__ __launch_bounds__(256, 2) void k_gemm(const float* __restrict__ x,
                                                 const float* __restrict__ w,
                                                 float* __restrict__ out,
                                                 int ostride, int cmul, int cadd0,
                                                 int bstride, int caddstep) {
    extern __shared__ float sm[];
    float* xs = sm;                 // [KC][XPAD] transposed x chunk
    float* ws = sm + KC * XPAD;     // [KC][64]
    int tid = threadIdx.x;
    int tx = tid & 15, ty = tid >> 4;
    int m0 = blockIdx.x * GROWS;
    const float* wb = w + (size_t)blockIdx.y * bstride;
    int cadd = cadd0 + blockIdx.y * caddstep;

    ull acc[4][4];
#pragma unroll
    for (int i = 0; i < 4; ++i)
#pragma unroll
        for (int j = 0; j < 4; ++j) acc[i][j] = 0ull;

    for (int kc = 0; kc < 2; ++kc) {
        if (kc) __syncthreads();
        const float4* w4 = (const float4*)(wb + kc * KC * 64);
        float4* ws4 = (float4*)ws;
        for (int i = tid; i < KC * 16; i += 256) ws4[i] = w4[i];
        const float4* x4 = (const float4*)x;
        for (int i = tid; i < GROWS * 32; i += 256) {
            int row = i >> 5, k4 = i & 31;
            int n = m0 + row;
            float4 v = make_float4(0.f, 0.f, 0.f, 0.f);
            if (n < NN) v = x4[n * 64 + kc * 32 + k4];
            xs[(k4 * 4 + 0) * XPAD + row] = v.x;
            xs[(k4 * 4 + 1) * XPAD + row] = v.y;
            xs[(k4 * 4 + 2) * XPAD + row] = v.z;
            xs[(k4 * 4 + 3) * XPAD + row] = v.w;
        }
        __syncthreads();

        const float* wp = ws + tx * 4;
        const float* xp = xs + ty * 8;
#pragma unroll 8
        for (int k = 0; k < KC; ++k) {
            float4 bv = *(const float4*)(wp + k * 64);
            const float* xr = xp + k * XPAD;
            ull a0 = *(const ull*)(xr);
            ull a1 = *(const ull*)(xr + 2);
            ull a2 = *(const ull*)(xr + 4);
            ull a3 = *(const ull*)(xr + 6);
            ull s0 = splat2(bv.x), s1 = splat2(bv.y),
                s2 = splat2(bv.z), s3 = splat2(bv.w);
            fma2(acc[0][0], a0, s0); fma2(acc[1][0], a1, s0);
            fma2(acc[2][0], a2, s0); fma2(acc[3][0], a3, s0);
            fma2(acc[0][1], a0, s1); fma2(acc[1][1], a1, s1);
            fma2(acc[2][1], a2, s1); fma2(acc[3][1], a3, s1);
            fma2(acc[0][2], a0, s2); fma2(acc[1][2], a1, s2);
            fma2(acc[2][2], a2, s2); fma2(acc[3][2], a3, s2);
            fma2(acc[0][3], a0, s3); fma2(acc[1][3], a1, s3);
            fma2(acc[2][3], a2, s3); fma2(acc[3][3], a3, s3);
        }
    }

    int col0 = tx * 4;
#pragma unroll
    for (int ip = 0; ip < 4; ++ip) {
        float lo[4], hi[4];
#pragma unroll
        for (int j = 0; j < 4; ++j) unpk2(lo[j], hi[j], acc[ip][j]);
        int n0 = m0 + ty * 8 + ip * 2;
        if (n0 < NN) {
            float* o = out + (size_t)n0 * ostride + cadd;
#pragma unroll
            for (int j = 0; j < 4; ++j) o[(col0 + j) * cmul] = lo[j];
        }
        if (n0 + 1 < NN) {
            float* o = out + (size_t)(n0 + 1) * ostride + cadd;
#pragma unroll
            for (int j = 0; j < 4; ++j) o[(col0 + j) * cmul] = hi[j];
        }
    }
}

// ---------------- K2: single-pass scan with sentinel lookback ----------------
__global__ __launch_bounds__(256) void k_scan() {
    int t = threadIdx.x, lane = t & 31, wid = t >> 5, bid = blockIdx.x;
    int i = bid * 256 + t;
    int v = (i < NN) ? g_deg[i] : 0;
    int inc = v;
#pragma unroll
    for (int o = 1; o < 32; o <<= 1) {
        int u = __shfl_up_sync(0xffffffffu, inc, o);
        if (lane >= o) inc += u;
    }
    __shared__ int ws[8], ws2[8], s_base;
    if (lane == 31) ws[wid] = inc;
    __syncthreads();
    if (t == 0) {
        int btot = 0;
#pragma unroll
        for (int w = 0; w < 8; ++w) btot += ws[w];
        atomicExch(&g_bsum[bid], -(btot + 1));
    }
    int part = 0;
    if (t < bid) {
        volatile int* vb = g_bsum;
        int sv;
        do { sv = vb[t]; } while (sv >= 0);
        part = -sv - 1;
    }
#pragma unroll
    for (int o = 16; o; o >>= 1) part += __shfl_xor_sync(0xffffffffu, part, o);
    if (lane == 0) ws2[wid] = part;
    __syncthreads();
    if (t == 0) {
        int b = 0;
#pragma unroll
        for (int w = 0; w < 8; ++w) b += ws2[w];
        s_base = b;
    }
    __syncthreads();
    int wpre = 0;
#pragma unroll
    for (int w = 0; w < 8; ++w) wpre += (w < wid) ? ws[w] : 0;
    int excl = s_base + wpre + inc - v;
    if (i < NN) { g_off[i] = excl; g_cur[i] = excl; g_deg[i] = 0; }
    if (bid == NBLK - 1 && t == 255) g_off[NN] = EE;
}

// ---------------- K3: scatter (packed), x4 vectorized + g_bsum reset -------
__global__ void k_scatter(const int* __restrict__ src,
                          const int* __restrict__ dst,
                          const int* __restrict__ rel) {
    int j = blockIdx.x * blockDim.x + threadIdx.x;
    if (j < EE / 4) {
        int4 s4 = ((const int4*)src)[j];
        int4 d4 = ((const int4*)dst)[j];
        int4 r4 = ((const int4*)rel)[j];
        int p;
        p = atomicAdd(&g_cur[d4.x], 1); g_packed[p] = s4.x | (r4.x << 16);
        p = atomicAdd(&g_cur[d4.y], 1); g_packed[p] = s4.y | (r4.y << 16);
        p = atomicAdd(&g_cur[d4.z], 1); g_packed[p] = s4.z | (r4.z << 16);
        p = atomicAdd(&g_cur[d4.w], 1); g_packed[p] = s4.w | (r4.w << 16);
    }
    if (blockIdx.x == 0 && threadIdx.x < NBLK) g_bsum[threadIdx.x] = 0;
}

// ---------------- K4: fused online-softmax aggregation ----------
// EXACT round-4 body: plain launch bounds, no occupancy cap, no load hoist.
__global__ __launch_bounds__(256) void k_agg(const float* __restrict__ coeff,
                                             float* __restrict__ out) {
    __shared__ __align__(16) float cf[CC * BB];  // cf[(r*4+h)*4 + b]
    int tid = threadIdx.x;
    if (tid < CC * BB) cf[tid] = coeff[tid];
    __syncthreads();

    int lane = tid & 31, w = tid >> 5;
    int n = blockIdx.x * 8 + w;
    if (n >= NN) return;

    int beg = g_off[n], end = g_off[n + 1];
    if (beg == end) {
        out[n * UU + lane] = 0.f;
        out[n * UU + 32 + lane] = 0.f;
        return;
    }

    const float* kn = g_qk + n * 64 + 32;

    ull acc[4][2][2];  // [head][u-half][b-pair]
#pragma unroll
    for (int a = 0; a < 4; ++a)
#pragma unroll
        for (int hf = 0; hf < 2; ++hf) { acc[a][hf][0] = 0ull; acc[a][hf][1] = 0ull; }

    float mx[4], dn[4];
#pragma unroll
    for (int a = 0; a < 4; ++a) { mx[a] = __int_as_float(0xff800000); dn[a] = 0.f; }

    int pk = g_packed[beg];

    for (int e = beg; e < end; ++e) {
        int pkc = pk;
        if (e + 1 < end) pk = g_packed[e + 1];

        int s = pkc & 0xFFFF, r = pkc >> 16;
        float4 q = *(const float4*)(g_qk + s * 64 + r * 4);
        float4 kk = *(const float4*)(kn + r * 4);
        float l[4];
        l[0] = q.x + kk.x; l[0] = l[0] > 0.f ? l[0] : 0.01f * l[0];
        l[1] = q.y + kk.y; l[1] = l[1] > 0.f ? l[1] : 0.01f * l[1];
        l[2] = q.z + kk.z; l[2] = l[2] > 0.f ? l[2] : 0.01f * l[2];
        l[3] = q.w + kk.w; l[3] = l[3] > 0.f ? l[3] : 0.01f * l[3];

        bool resc = false;
        float nmx[4];
#pragma unroll
        for (int a = 0; a < 4; ++a) {
            nmx[a] = fmaxf(mx[a], l[a]);
            resc |= (nmx[a] != mx[a]);
        }
        if (resc) {  // warp-uniform branch (l is uniform across lanes)
#pragma unroll
            for (int a = 0; a < 4; ++a) {
                float sc = __expf(mx[a] - nmx[a]);  // exp(-inf)=0 on first edge
                dn[a] *= sc;
                ull sc2 = splat2(sc);
                acc[a][0][0] = mul2(acc[a][0][0], sc2);
                acc[a][0][1] = mul2(acc[a][0][1], sc2);
                acc[a][1][0] = mul2(acc[a][1][0], sc2);
                acc[a][1][1] = mul2(acc[a][1][1], sc2);
                mx[a] = nmx[a];
            }
        }

        float wv[4];
#pragma unroll
        for (int a = 0; a < 4; ++a) {
            wv[a] = __expf(l[a] - mx[a]);
            dn[a] += wv[a];
        }

        const float4* yr = (const float4*)(g_y + (size_t)s * 256);
        float4 y0 = yr[lane];        // u = lane,    b0..b3
        float4 y1 = yr[32 + lane];   // u = lane+32, b0..b3
        ull y00 = pack2(y0.x, y0.y), y01 = pack2(y0.z, y0.w);
        ull y10 = pack2(y1.x, y1.y), y11 = pack2(y1.z, y1.w);
        const ull* cr = (const ull*)(cf + r * 16);
#pragma unroll
        for (int a = 0; a < 4; ++a) {
            ull wa = splat2(wv[a]);
            ull c0 = mul2(wa, cr[a * 2]);
            ull c1 = mul2(wa, cr[a * 2 + 1]);
            fma2(acc[a][0][0], c0, y00);
            fma2(acc[a][0][1], c1, y01);
            fma2(acc[a][1][0], c0, y10);
            fma2(acc[a][1][1], c1, y11);
        }
    }

    float o0 = 0.f, o1 = 0.f;
#pragma unroll
    for (int a = 0; a < 4; ++a) {
        float inv = 1.f / fmaxf(dn[a], 1e-16f);
        float l0, h0, l1, h1, l2, h2, l3, h3;
        unpk2(l0, h0, acc[a][0][0]);
        unpk2(l1, h1, acc[a][0][1]);
        unpk2(l2, h2, acc[a][1][0]);
        unpk2(l3, h3, acc[a][1][1]);
        o0 += inv * ((l0 + h0) + (l1 + h1));
        o1 += inv * ((l2 + h2) + (l3 + h3));
    }
    out[n * UU + lane] = 0.25f * o0;
    out[n * UU + 32 + lane] = 0.25f * o1;
}

// ---------------- launch ----------------
extern "C" void kernel_launch(void* const* d_in, const int* in_sizes, int n_in,
                              void* d_out, int out_size) {
    const float* x     = (const float*)d_in[0];
    const float* basis = (const float*)d_in[1];
    const float* coeff = (const float*)d_in[2];
    const float* aq    = (const float*)d_in[3];
    const float* ak    = (const float*)d_in[4];
    const int*   src   = (const int*)d_in[5];
    const int*   dst   = (const int*)d_in[6];
    const int*   rel   = (const int*)d_in[7];
    float* out = (float*)d_out;

    float* d_y;   cudaGetSymbolAddress((void**)&d_y, g_y);
    float* d_qk;  cudaGetSymbolAddress((void**)&d_qk, g_qk);
    float* d_wqk; cudaGetSymbolAddress((void**)&d_wqk, g_wqk);

    cudaFuncSetAttribute(k_gemm, cudaFuncAttributeMaxDynamicSharedMemorySize, GEMM_SMEM);

    cudaStream_t s1 = 0, s2 = 0;
    bool fork = s_forkOK;
    if (fork) {
        s1 = s_s1; s2 = s_s2;
        cudaEventRecord(s_evRoot, 0);
        cudaStreamWaitEvent(s1, s_evRoot, 0);
        cudaStreamWaitEvent(s2, s_evRoot, 0);
    }

    // --- side stream 2: y GEMM (independent of everything else) ---
    k_gemm<<<dim3((NN + GROWS - 1) / GROWS, BB), 256, GEMM_SMEM, s2>>>(
        x, basis, d_y, 256, 4, 0, FF * UU, 1);

    // --- main stream: prep + hist fused ---
    k_misc<<<32 + HBLK, 256>>>(coeff, basis, aq, ak, dst);
    if (fork) {
        cudaEventRecord(s_evMisc, 0);
        cudaStreamWaitEvent(s1, s_evMisc, 0);
    }

    // --- side stream 1: qk GEMM (needs g_wqk from misc) ---
    k_gemm<<<dim3((NN + GROWS - 1) / GROWS, 1), 256, GEMM_SMEM, s1>>>(
        x, d_wqk, d_qk, 64, 1, 0, 0, 0);

    if (fork) {
        cudaEventRecord(s_evA, s1);
        cudaEventRecord(s_evB, s2);
    }

    // --- main stream: scan + scatter ---
    k_scan<<<NBLK, 256>>>();
    k_scatter<<<(EE / 4 + 255) / 256, 256>>>(src, dst, rel);

    if (fork) {
        cudaStreamWaitEvent(0, s_evA, 0);
        cudaStreamWaitEvent(0, s_evB, 0);
    }
    k_agg<<<(NN + 7) / 8, 256>>>(coeff, out);
}

// round 8
// speedup vs baseline: 2.8168x; 1.3029x over previous
#include <cuda_runtime.h>

#define NN 20000
#define FF 256
#define RR 8
#define HH 4
#define UU 64
#define BB 4
#define CC 32   // R*H
#define EE 320000
#define NBLK 79  // ceil(NN/256)

typedef unsigned long long ull;

// ---------------- f32x2 packed math helpers ----------------
__device__ __forceinline__ ull splat2(float v) {
    ull r; asm("mov.b64 %0, {%1, %1};" : "=l"(r) : "f"(v)); return r;
}
__device__ __forceinline__ ull pack2(float lo, float hi) {
    ull r; asm("mov.b64 %0, {%1, %2};" : "=l"(r) : "f"(lo), "f"(hi)); return r;
}
__device__ __forceinline__ void fma2(ull& d, ull a, ull b) {
    asm("fma.rn.f32x2 %0, %1, %2, %0;" : "+l"(d) : "l"(a), "l"(b));
}
__device__ __forceinline__ ull mul2(ull a, ull b) {
    ull d; asm("mul.rn.f32x2 %0, %1, %2;" : "=l"(d) : "l"(a), "l"(b)); return d;
}
__device__ __forceinline__ void unpk2(float& lo, float& hi, ull v) {
    asm("mov.b64 {%0, %1}, %2;" : "=f"(lo), "=f"(hi) : "l"(v));
}

// ---------------- device scratch ----------------
__device__ float  g_y[NN * BB * UU];   // y[n][u*4 + b]  (interleaved, 20.48 MB)
__device__ float  g_qk[NN * 64];       // [n][c] c<32: q(c=r*4+h), c>=32: k
__device__ float  g_wqk[FF * 64];      // [f][c] k-major weight for qk GEMM
__device__ int    g_deg[NN];
__device__ int    g_off[NN + 1];
__device__ int    g_cur[NN];
__device__ int    g_bsum[NBLK];
__device__ int    g_boff[NBLK];
__device__ int    g_packed[EE];        // src | (rel<<16), CSR-sorted by dst

// ---------------- static stream/event bootstrap ----------------
static cudaStream_t s_s1 = 0, s_s2 = 0;
static cudaEvent_t  s_evRoot = 0, s_evA = 0, s_evB = 0;
static bool s_forkOK = false;
namespace {
struct Boot {
    Boot() {
        bool ok = true;
        ok &= (cudaStreamCreateWithFlags(&s_s1, cudaStreamNonBlocking) == cudaSuccess);
        ok &= (cudaStreamCreateWithFlags(&s_s2, cudaStreamNonBlocking) == cudaSuccess);
        ok &= (cudaEventCreateWithFlags(&s_evRoot, cudaEventDisableTiming) == cudaSuccess);
        ok &= (cudaEventCreateWithFlags(&s_evA, cudaEventDisableTiming) == cudaSuccess);
        ok &= (cudaEventCreateWithFlags(&s_evB, cudaEventDisableTiming) == cudaSuccess);
        s_forkOK = ok;
    }
} s_boot;
}

// ---------------- K0: qk weight build ----------------
__global__ void k_prep(const float* __restrict__ coeff,
                       const float* __restrict__ basis,
                       const float* __restrict__ aq,
                       const float* __restrict__ ak) {
    int idx = blockIdx.x * blockDim.x + threadIdx.x;
    if (idx >= CC * FF) return;
    int c = idx >> 8;       // /FF
    int f = idx & 255;      // %FF
    float sq = 0.f, sk = 0.f;
#pragma unroll
    for (int b = 0; b < BB; ++b) {
        const float* bp = basis + (b * FF + f) * UU;
        const float* aqc = aq + c * UU;
        const float* akc = ak + c * UU;
        float dq = 0.f, dk = 0.f;
#pragma unroll 8
        for (int u = 0; u < UU; ++u) {
            float bv = bp[u];
            dq += bv * aqc[u];
            dk += bv * akc[u];
        }
        float cb = coeff[c * BB + b];
        sq += cb * dq;
        sk += cb * dk;
    }
    g_wqk[f * 64 + c]      = sq;
    g_wqk[f * 64 + 32 + c] = sk;
}

// ---------------- K1: generic 128x64 FFMA2 GEMM ----------------
#define GROWS 128
#define KC 128
#define XPAD 132
#define GEMM_SMEM ((KC * XPAD + KC * 64) * 4)

__global__ __launch_bounds__(256, 2) void k_gemm(const float* __restrict__ x,
                                                 const float* __restrict__ w,
                                                 float* __restrict__ out,
                                                 int ostride, int cmul, int cadd0,
                                                 int bstride, int caddstep) {
    extern __shared__ float sm[];
    float* xs = sm;                 // [KC][XPAD] transposed x chunk
    float* ws = sm + KC * XPAD;     // [KC][64]
    int tid = threadIdx.x;
    int tx = tid & 15, ty = tid >> 4;
    int m0 = blockIdx.x * GROWS;
    const float* wb = w + (size_t)blockIdx.y * bstride;
    int cadd = cadd0 + blockIdx.y * caddstep;

    ull acc[4][4];
#pragma unroll
    for (int i = 0; i < 4; ++i)
#pragma unroll
        for (int j = 0; j < 4; ++j) acc[i][j] = 0ull;

    for (int kc = 0; kc < 2; ++kc) {
        if (kc) __syncthreads();
        const float4* w4 = (const float4*)(wb + kc * KC * 64);
        float4* ws4 = (float4*)ws;
        for (int i = tid; i < KC * 16; i += 256) ws4[i] = w4[i];
        const float4* x4 = (const float4*)x;
        for (int i = tid; i < GROWS * 32; i += 256) {
            int row = i >> 5, k4 = i & 31;
            int n = m0 + row;
            float4 v = make_float4(0.f, 0.f, 0.f, 0.f);
            if (n < NN) v = x4[n * 64 + kc * 32 + k4];
            xs[(k4 * 4 + 0) * XPAD + row] = v.x;
            xs[(k4 * 4 + 1) * XPAD + row] = v.y;
            xs[(k4 * 4 + 2) * XPAD + row] = v.z;
            xs[(k4 * 4 + 3) * XPAD + row] = v.w;
        }
        __syncthreads();

        const float* wp = ws + tx * 4;
        const float* xp = xs + ty * 8;
#pragma unroll 8
        for (int k = 0; k < KC; ++k) {
            float4 bv = *(const float4*)(wp + k * 64);
            const float* xr = xp + k * XPAD;
            ull a0 = *(const ull*)(xr);
            ull a1 = *(const ull*)(xr + 2);
            ull a2 = *(const ull*)(xr + 4);
            ull a3 = *(const ull*)(xr + 6);
            ull s0 = splat2(bv.x), s1 = splat2(bv.y),
                s2 = splat2(bv.z), s3 = splat2(bv.w);
            fma2(acc[0][0], a0, s0); fma2(acc[1][0], a1, s0);
            fma2(acc[2][0], a2, s0); fma2(acc[3][0], a3, s0);
            fma2(acc[0][1], a0, s1); fma2(acc[1][1], a1, s1);
            fma2(acc[2][1], a2, s1); fma2(acc[3][1], a3, s1);
            fma2(acc[0][2], a0, s2); fma2(acc[1][2], a1, s2);
            fma2(acc[2][2], a2, s2); fma2(acc[3][2], a3, s2);
            fma2(acc[0][3], a0, s3); fma2(acc[1][3], a1, s3);
            fma2(acc[2][3], a2, s3); fma2(acc[3][3], a3, s3);
        }
    }

    int col0 = tx * 4;
#pragma unroll
    for (int ip = 0; ip < 4; ++ip) {
        float lo[4], hi[4];
#pragma unroll
        for (int j = 0; j < 4; ++j) unpk2(lo[j], hi[j], acc[ip][j]);
        int n0 = m0 + ty * 8 + ip * 2;
        if (n0 < NN) {
            float* o = out + (size_t)n0 * ostride + cadd;
#pragma unroll
            for (int j = 0; j < 4; ++j) o[(col0 + j) * cmul] = lo[j];
        }
        if (n0 + 1 < NN) {
            float* o = out + (size_t)(n0 + 1) * ostride + cadd;
#pragma unroll
            for (int j = 0; j < 4; ++j) o[(col0 + j) * cmul] = hi[j];
        }
    }
}

// ---------------- counting sort: hist + 3-phase parallel scan ----------------
__global__ void k_hist(const int* __restrict__ dst) {
    int i = blockIdx.x * blockDim.x + threadIdx.x;
    if (i * 4 < EE) {
        int4 d4 = ((const int4*)dst)[i];
        atomicAdd(&g_deg[d4.x], 1);
        atomicAdd(&g_deg[d4.y], 1);
        atomicAdd(&g_deg[d4.z], 1);
        atomicAdd(&g_deg[d4.w], 1);
    }
}

__global__ void k_scanA() {   // per-block sums
    int i = blockIdx.x * 256 + threadIdx.x;
    int v = (i < NN) ? g_deg[i] : 0;
#pragma unroll
    for (int o = 16; o; o >>= 1) v += __shfl_xor_sync(0xffffffffu, v, o);
    __shared__ int ws[8];
    if ((threadIdx.x & 31) == 0) ws[threadIdx.x >> 5] = v;
    __syncthreads();
    if (threadIdx.x == 0) {
        int s = 0;
#pragma unroll
        for (int w = 0; w < 8; ++w) s += ws[w];
        g_bsum[blockIdx.x] = s;
    }
}

__global__ void k_scanB() {   // 1 warp scans NBLK block sums
    int lane = threadIdx.x;
    int carry = 0;
    for (int base = 0; base < NBLK; base += 32) {
        int i = base + lane;
        int v = (i < NBLK) ? g_bsum[i] : 0;
        int inc = v;
#pragma unroll
        for (int o = 1; o < 32; o <<= 1) {
            int u = __shfl_up_sync(0xffffffffu, inc, o);
            if (lane >= o) inc += u;
        }
        if (i < NBLK) g_boff[i] = carry + inc - v;
        carry += __shfl_sync(0xffffffffu, inc, 31);
    }
    if (lane == 0) g_off[NN] = EE;
}

__global__ void k_scanC() {   // local exclusive scan + base
    int t = threadIdx.x, lane = t & 31, wid = t >> 5;
    int i = blockIdx.x * 256 + t;
    int v = (i < NN) ? g_deg[i] : 0;
    int inc = v;
#pragma unroll
    for (int o = 1; o < 32; o <<= 1) {
        int u = __shfl_up_sync(0xffffffffu, inc, o);
        if (lane >= o) inc += u;
    }
    __shared__ int ws[8];
    if (lane == 31) ws[wid] = inc;
    __syncthreads();
    int wbase = 0;
#pragma unroll
    for (int w = 0; w < 8; ++w) wbase += (w < wid) ? ws[w] : 0;
    int excl = g_boff[blockIdx.x] + wbase + inc - v;
    if (i < NN) { g_off[i] = excl; g_cur[i] = excl; }
}

// ---------------- scatter (packed only) ----------------
__global__ void k_scatter(const int* __restrict__ src,
                          const int* __restrict__ dst,
                          const int* __restrict__ rel) {
    int e = blockIdx.x * blockDim.x + threadIdx.x;
    if (e >= EE) return;
    int s = src[e], d = dst[e], r = rel[e];
    int p = atomicAdd(&g_cur[d], 1);
    g_packed[p] = s | (r << 16);
}

// ---------------- fused online-softmax aggregation: 2 warps per node --------
// Warp pair (A=even, B=odd) splits the node's CSR segment in half; each runs
// the round-4 online-softmax loop on its half; merge via (mx,dn) exchange in
// smem + 64-float partial from warp B. Halves the per-warp edge latency chain.
__global__ __launch_bounds__(256) void k_agg(const float* __restrict__ coeff,
                                             float* __restrict__ out) {
    __shared__ __align__(16) float cf[CC * BB];      // cf[(r*4+h)*4 + b]
    __shared__ float s_mxdn[4][2][8];                // [node][sub][mx0-3,dn0-3]
    __shared__ float s_part[4][64];                  // warp B partial output
    int tid = threadIdx.x;
    if (tid < CC * BB) cf[tid] = coeff[tid];

    int lane = tid & 31, w = tid >> 5;
    int node = w >> 1;           // 0..3 within block
    int sub = w & 1;             // 0 = warp A, 1 = warp B
    int n = blockIdx.x * 4 + node;
    bool active = (n < NN);

    int beg = 0, end = 0;
    if (active) { beg = g_off[n]; end = g_off[n + 1]; }
    int len = end - beg;
    int half = (len + 1) >> 1;
    int mybeg = beg + (sub ? half : 0);
    int myend = sub ? end : (beg + half);

    __syncthreads();  // cf visible

    const float* kn = g_qk + n * 64 + 32;

    ull acc[4][2][2];  // [head][u-half][b-pair]
#pragma unroll
    for (int a = 0; a < 4; ++a)
#pragma unroll
        for (int hf = 0; hf < 2; ++hf) { acc[a][hf][0] = 0ull; acc[a][hf][1] = 0ull; }

    float mx[4], dn[4];
#pragma unroll
    for (int a = 0; a < 4; ++a) { mx[a] = __int_as_float(0xff800000); dn[a] = 0.f; }

    if (mybeg < myend) {
        int pk = g_packed[mybeg];
        for (int e = mybeg; e < myend; ++e) {
            int pkc = pk;
            if (e + 1 < myend) pk = g_packed[e + 1];

            int s = pkc & 0xFFFF, r = pkc >> 16;
            float4 q = *(const float4*)(g_qk + s * 64 + r * 4);
            float4 kk = *(const float4*)(kn + r * 4);
            float l[4];
            l[0] = q.x + kk.x; l[0] = l[0] > 0.f ? l[0] : 0.01f * l[0];
            l[1] = q.y + kk.y; l[1] = l[1] > 0.f ? l[1] : 0.01f * l[1];
            l[2] = q.z + kk.z; l[2] = l[2] > 0.f ? l[2] : 0.01f * l[2];
            l[3] = q.w + kk.w; l[3] = l[3] > 0.f ? l[3] : 0.01f * l[3];

            bool resc = false;
            float nmx[4];
#pragma unroll
            for (int a = 0; a < 4; ++a) {
                nmx[a] = fmaxf(mx[a], l[a]);
                resc |= (nmx[a] != mx[a]);
            }
            if (resc) {  // warp-uniform branch
#pragma unroll
                for (int a = 0; a < 4; ++a) {
                    float sc = __expf(mx[a] - nmx[a]);  // exp(-inf)=0 first edge
                    dn[a] *= sc;
                    ull sc2 = splat2(sc);
                    acc[a][0][0] = mul2(acc[a][0][0], sc2);
                    acc[a][0][1] = mul2(acc[a][0][1], sc2);
                    acc[a][1][0] = mul2(acc[a][1][0], sc2);
                    acc[a][1][1] = mul2(acc[a][1][1], sc2);
                    mx[a] = nmx[a];
                }
            }

            float wv[4];
#pragma unroll
            for (int a = 0; a < 4; ++a) {
                wv[a] = __expf(l[a] - mx[a]);
                dn[a] += wv[a];
            }

            const float4* yr = (const float4*)(g_y + (size_t)s * 256);
            float4 y0 = yr[lane];        // u = lane,    b0..b3
            float4 y1 = yr[32 + lane];   // u = lane+32, b0..b3
            ull y00 = pack2(y0.x, y0.y), y01 = pack2(y0.z, y0.w);
            ull y10 = pack2(y1.x, y1.y), y11 = pack2(y1.z, y1.w);
            const ull* cr = (const ull*)(cf + r * 16);
#pragma unroll
            for (int a = 0; a < 4; ++a) {
                ull wa = splat2(wv[a]);
                ull c0 = mul2(wa, cr[a * 2]);
                ull c1 = mul2(wa, cr[a * 2 + 1]);
                fma2(acc[a][0][0], c0, y00);
                fma2(acc[a][0][1], c1, y01);
                fma2(acc[a][1][0], c0, y10);
                fma2(acc[a][1][1], c1, y11);
            }
        }
    }

    // ---- exchange (mx, dn) between the warp pair ----
    if (lane == 0) {
        s_mxdn[node][sub][0] = mx[0]; s_mxdn[node][sub][1] = mx[1];
        s_mxdn[node][sub][2] = mx[2]; s_mxdn[node][sub][3] = mx[3];
        s_mxdn[node][sub][4] = dn[0]; s_mxdn[node][sub][5] = dn[1];
        s_mxdn[node][sub][6] = dn[2]; s_mxdn[node][sub][7] = dn[3];
    }
    __syncthreads();

    float o0 = 0.f, o1 = 0.f;
    if (active && len > 0) {
        const float* other = s_mxdn[node][1 - sub];
#pragma unroll
        for (int a = 0; a < 4; ++a) {
            float mo = other[a], dno = other[4 + a];
            float m = fmaxf(mx[a], mo);
            float eself = __expf(mx[a] - m);   // 0 if this half empty
            float eo = __expf(mo - m);
            float dt = dn[a] * eself + dno * eo;
            float scl = eself / fmaxf(dt, 1e-16f);
            float l0, h0, l1, h1, l2, h2, l3, h3;
            unpk2(l0, h0, acc[a][0][0]);
            unpk2(l1, h1, acc[a][0][1]);
            unpk2(l2, h2, acc[a][1][0]);
            unpk2(l3, h3, acc[a][1][1]);
            o0 += scl * ((l0 + h0) + (l1 + h1));
            o1 += scl * ((l2 + h2) + (l3 + h3));
        }
    }

    if (sub == 1) {
        s_part[node][lane] = o0;
        s_part[node][32 + lane] = o1;
    }
    __syncthreads();

    if (sub == 0 && active) {
        if (len == 0) {
            out[n * UU + lane] = 0.f;
            out[n * UU + 32 + lane] = 0.f;
        } else {
            o0 += s_part[node][lane];
            o1 += s_part[node][32 + lane];
            out[n * UU + lane] = 0.25f * o0;
            out[n * UU + 32 + lane] = 0.25f * o1;
        }
    }
}

// ---------------- launch (exact round-4 structure) ----------------
extern "C" void kernel_launch(void* const* d_in, const int* in_sizes, int n_in,
                              void* d_out, int out_size) {
    const float* x     = (const float*)d_in[0];
    const float* basis = (const float*)d_in[1];
    const float* coeff = (const float*)d_in[2];
    const float* aq    = (const float*)d_in[3];
    const float* ak    = (const float*)d_in[4];
    const int*   src   = (const int*)d_in[5];
    const int*   dst   = (const int*)d_in[6];
    const int*   rel   = (const int*)d_in[7];
    float* out = (float*)d_out;

    float* d_y;   cudaGetSymbolAddress((void**)&d_y, g_y);
    float* d_qk;  cudaGetSymbolAddress((void**)&d_qk, g_qk);
    float* d_wqk; cudaGetSymbolAddress((void**)&d_wqk, g_wqk);
    int*   d_deg; cudaGetSymbolAddress((void**)&d_deg, g_deg);

    cudaFuncSetAttribute(k_gemm, cudaFuncAttributeMaxDynamicSharedMemorySize, GEMM_SMEM);

    cudaStream_t s1 = 0, s2 = 0;
    bool fork = s_forkOK;
    if (fork) {
        s1 = s_s1; s2 = s_s2;
        cudaEventRecord(s_evRoot, 0);
        cudaStreamWaitEvent(s1, s_evRoot, 0);
        cudaStreamWaitEvent(s2, s_evRoot, 0);
    }

    // --- side stream 1: prep -> qk GEMM ---
    k_prep<<<(CC * FF + 255) / 256, 256, 0, s1>>>(coeff, basis, aq, ak);
    k_gemm<<<dim3((NN + GROWS - 1) / GROWS, 1), 256, GEMM_SMEM, s1>>>(
        x, d_wqk, d_qk, 64, 1, 0, 0, 0);

    // --- side stream 2: y GEMM ---
    k_gemm<<<dim3((NN + GROWS - 1) / GROWS, BB), 256, GEMM_SMEM, s2>>>(
        x, basis, d_y, 256, 4, 0, FF * UU, 1);

    if (fork) {
        cudaEventRecord(s_evA, s1);
        cudaEventRecord(s_evB, s2);
    }

    // --- main stream: counting sort ---
    cudaMemsetAsync(d_deg, 0, NN * sizeof(int), 0);
    k_hist<<<(EE / 4 + 255) / 256, 256>>>(dst);
    k_scanA<<<NBLK, 256>>>();
    k_scanB<<<1, 32>>>();
    k_scanC<<<NBLK, 256>>>();
    k_scatter<<<(EE + 255) / 256, 256>>>(src, dst, rel);

    if (fork) {
        cudaStreamWaitEvent(0, s_evA, 0);
        cudaStreamWaitEvent(0, s_evB, 0);
    }
    k_agg<<<(NN + 3) / 4, 256>>>(coeff, out);
}

// round 9
// speedup vs baseline: 2.8188x; 1.0007x over previous
#include <cuda_runtime.h>

#define NN 20000
#define FF 256
#define RR 8
#define HH 4
#define UU 64
#define BB 4
#define CC 32   // R*H
#define EE 320000
#define NBLK 79  // ceil(NN/256)

typedef unsigned long long ull;

// ---------------- f32x2 packed math helpers ----------------
__device__ __forceinline__ ull splat2(float v) {
    ull r; asm("mov.b64 %0, {%1, %1};" : "=l"(r) : "f"(v)); return r;
}
__device__ __forceinline__ ull pack2(float lo, float hi) {
    ull r; asm("mov.b64 %0, {%1, %2};" : "=l"(r) : "f"(lo), "f"(hi)); return r;
}
__device__ __forceinline__ void fma2(ull& d, ull a, ull b) {
    asm("fma.rn.f32x2 %0, %1, %2, %0;" : "+l"(d) : "l"(a), "l"(b));
}
__device__ __forceinline__ ull mul2(ull a, ull b) {
    ull d; asm("mul.rn.f32x2 %0, %1, %2;" : "=l"(d) : "l"(a), "l"(b)); return d;
}
__device__ __forceinline__ void unpk2(float& lo, float& hi, ull v) {
    asm("mov.b64 {%0, %1}, %2;" : "=f"(lo), "=f"(hi) : "l"(v));
}

// ---------------- device scratch ----------------
__device__ float  g_y[NN * BB * UU];   // y[n][u*4 + b]  (interleaved, 20.48 MB)
__device__ float  g_qk[NN * 64];       // [n][c] c<32: q(c=r*4+h), c>=32: k
__device__ float  g_wqk[FF * 64];      // [f][c] k-major weight for qk GEMM
__device__ int    g_deg[NN];
__device__ int    g_off[NN + 1];
__device__ int    g_cur[NN];
__device__ int    g_bsum[NBLK];
__device__ int    g_boff[NBLK];
__device__ int    g_packed[EE];        // src | (rel<<16), CSR-sorted by dst

// ---------------- static stream/event bootstrap ----------------
static cudaStream_t s_s1 = 0, s_s2 = 0;
static cudaEvent_t  s_evRoot = 0, s_evA = 0, s_evB = 0;
static bool s_forkOK = false;
namespace {
struct Boot {
    Boot() {
        bool ok = true;
        ok &= (cudaStreamCreateWithFlags(&s_s1, cudaStreamNonBlocking) == cudaSuccess);
        ok &= (cudaStreamCreateWithFlags(&s_s2, cudaStreamNonBlocking) == cudaSuccess);
        ok &= (cudaEventCreateWithFlags(&s_evRoot, cudaEventDisableTiming) == cudaSuccess);
        ok &= (cudaEventCreateWithFlags(&s_evA, cudaEventDisableTiming) == cudaSuccess);
        ok &= (cudaEventCreateWithFlags(&s_evB, cudaEventDisableTiming) == cudaSuccess);
        s_forkOK = ok;
    }
} s_boot;
}

// ---------------- K0: qk weight build (smem-staged, coalesced) ----------------
// 32 blocks x 256 threads. Block bi owns f in [bi*8, bi*8+8).
// Stage basis slice + aq/ak into smem ONCE (coalesced), then each thread
// computes one (c, f_local) pair. All smem reads bank-conflict-free.
__global__ __launch_bounds__(256) void k_prep(const float* __restrict__ coeff,
                                              const float* __restrict__ basis,
                                              const float* __restrict__ aq,
                                              const float* __restrict__ ak) {
    __shared__ float bs[BB][8][UU + 1];      // padded: fl varies -> distinct banks
    __shared__ float aqs[CC][UU + 1];
    __shared__ float aks[CC][UU + 1];
    int t = threadIdx.x;
    int f_base = blockIdx.x * 8;

    for (int i = t; i < CC * UU; i += 256) {
        int c = i >> 6, u = i & 63;
        aqs[c][u] = aq[i];
        aks[c][u] = ak[i];
    }
    for (int i = t; i < BB * 8 * UU; i += 256) {
        int b = i >> 9;
        int rem = i & 511;
        int fl = rem >> 6, u = rem & 63;
        bs[b][fl][u] = basis[(b * FF + f_base + fl) * UU + u];
    }
    __syncthreads();

    int c = t >> 3, fl = t & 7;
    float sq = 0.f, sk = 0.f;
#pragma unroll
    for (int b = 0; b < BB; ++b) {
        float dq = 0.f, dk = 0.f;
        const float* bp = bs[b][fl];
        const float* aqc = aqs[c];
        const float* akc = aks[c];
#pragma unroll 8
        for (int u = 0; u < UU; ++u) {
            float bv = bp[u];
            dq += bv * aqc[u];
            dk += bv * akc[u];
        }
        float cb = coeff[c * BB + b];
        sq += cb * dq;
        sk += cb * dk;
    }
    int f = f_base + fl;
    g_wqk[f * 64 + c]      = sq;
    g_wqk[f * 64 + 32 + c] = sk;
}

// ---------------- K1: generic 128x64 FFMA2 GEMM ----------------
#define GROWS 128
#define KC 128
#define XPAD 132
#define GEMM_SMEM ((KC * XPAD + KC * 64) * 4)

__global__ __launch_bounds__(256, 2) void k_gemm(const float* __restrict__ x,
                                                 const float* __restrict__ w,
                                                 float* __restrict__ out,
                                                 int ostride, int cmul, int cadd0,
                                                 int bstride, int caddstep) {
    extern __shared__ float sm[];
    float* xs = sm;                 // [KC][XPAD] transposed x chunk
    float* ws = sm + KC * XPAD;     // [KC][64]
    int tid = threadIdx.x;
    int tx = tid & 15, ty = tid >> 4;
    int m0 = blockIdx.x * GROWS;
    const float* wb = w + (size_t)blockIdx.y * bstride;
    int cadd = cadd0 + blockIdx.y * caddstep;

    ull acc[4][4];
#pragma unroll
    for (int i = 0; i < 4; ++i)
#pragma unroll
        for (int j = 0; j < 4; ++j) acc[i][j] = 0ull;

    for (int kc = 0; kc < 2; ++kc) {
        if (kc) __syncthreads();
        const float4* w4 = (const float4*)(wb + kc * KC * 64);
        float4* ws4 = (float4*)ws;
        for (int i = tid; i < KC * 16; i += 256) ws4[i] = w4[i];
        const float4* x4 = (const float4*)x;
        for (int i = tid; i < GROWS * 32; i += 256) {
            int row = i >> 5, k4 = i & 31;
            int n = m0 + row;
            float4 v = make_float4(0.f, 0.f, 0.f, 0.f);
            if (n < NN) v = x4[n * 64 + kc * 32 + k4];
            xs[(k4 * 4 + 0) * XPAD + row] = v.x;
            xs[(k4 * 4 + 1) * XPAD + row] = v.y;
            xs[(k4 * 4 + 2) * XPAD + row] = v.z;
            xs[(k4 * 4 + 3) * XPAD + row] = v.w;
        }
        __syncthreads();

        const float* wp = ws + tx * 4;
        const float* xp = xs + ty * 8;
#pragma unroll 8
        for (int k = 0; k < KC; ++k) {
            float4 bv = *(const float4*)(wp + k * 64);
            const float* xr = xp + k * XPAD;
            ull a0 = *(const ull*)(xr);
            ull a1 = *(const ull*)(xr + 2);
            ull a2 = *(const ull*)(xr + 4);
            ull a3 = *(const ull*)(xr + 6);
            ull s0 = splat2(bv.x), s1 = splat2(bv.y),
                s2 = splat2(bv.z), s3 = splat2(bv.w);
            fma2(acc[0][0], a0, s0); fma2(acc[1][0], a1, s0);
            fma2(acc[2][0], a2, s0); fma2(acc[3][0], a3, s0);
            fma2(acc[0][1], a0, s1); fma2(acc[1][1], a1, s1);
            fma2(acc[2][1], a2, s1); fma2(acc[3][1], a3, s1);
            fma2(acc[0][2], a0, s2); fma2(acc[1][2], a1, s2);
            fma2(acc[2][2], a2, s2); fma2(acc[3][2], a3, s2);
            fma2(acc[0][3], a0, s3); fma2(acc[1][3], a1, s3);
            fma2(acc[2][3], a2, s3); fma2(acc[3][3], a3, s3);
        }
    }

    int col0 = tx * 4;
#pragma unroll
    for (int ip = 0; ip < 4; ++ip) {
        float lo[4], hi[4];
#pragma unroll
        for (int j = 0; j < 4; ++j) unpk2(lo[j], hi[j], acc[ip][j]);
        int n0 = m0 + ty * 8 + ip * 2;
        if (n0 < NN) {
            float* o = out + (size_t)n0 * ostride + cadd;
#pragma unroll
            for (int j = 0; j < 4; ++j) o[(col0 + j) * cmul] = lo[j];
        }
        if (n0 + 1 < NN) {
            float* o = out + (size_t)(n0 + 1) * ostride + cadd;
#pragma unroll
            for (int j = 0; j < 4; ++j) o[(col0 + j) * cmul] = hi[j];
        }
    }
}

// ---------------- counting sort: hist + 3-phase parallel scan ----------------
__global__ void k_hist(const int* __restrict__ dst) {
    int i = blockIdx.x * blockDim.x + threadIdx.x;
    if (i * 4 < EE) {
        int4 d4 = ((const int4*)dst)[i];
        atomicAdd(&g_deg[d4.x], 1);
        atomicAdd(&g_deg[d4.y], 1);
        atomicAdd(&g_deg[d4.z], 1);
        atomicAdd(&g_deg[d4.w], 1);
    }
}

__global__ void k_scanA() {   // per-block sums
    int i = blockIdx.x * 256 + threadIdx.x;
    int v = (i < NN) ? g_deg[i] : 0;
#pragma unroll
    for (int o = 16; o; o >>= 1) v += __shfl_xor_sync(0xffffffffu, v, o);
    __shared__ int ws[8];
    if ((threadIdx.x & 31) == 0) ws[threadIdx.x >> 5] = v;
    __syncthreads();
    if (threadIdx.x == 0) {
        int s = 0;
#pragma unroll
        for (int w = 0; w < 8; ++w) s += ws[w];
        g_bsum[blockIdx.x] = s;
    }
}

__global__ void k_scanB() {   // 1 warp scans NBLK block sums
    int lane = threadIdx.x;
    int carry = 0;
    for (int base = 0; base < NBLK; base += 32) {
        int i = base + lane;
        int v = (i < NBLK) ? g_bsum[i] : 0;
        int inc = v;
#pragma unroll
        for (int o = 1; o < 32; o <<= 1) {
            int u = __shfl_up_sync(0xffffffffu, inc, o);
            if (lane >= o) inc += u;
        }
        if (i < NBLK) g_boff[i] = carry + inc - v;
        carry += __shfl_sync(0xffffffffu, inc, 31);
    }
    if (lane == 0) g_off[NN] = EE;
}

__global__ void k_scanC() {   // local exclusive scan + base
    int t = threadIdx.x, lane = t & 31, wid = t >> 5;
    int i = blockIdx.x * 256 + t;
    int v = (i < NN) ? g_deg[i] : 0;
    int inc = v;
#pragma unroll
    for (int o = 1; o < 32; o <<= 1) {
        int u = __shfl_up_sync(0xffffffffu, inc, o);
        if (lane >= o) inc += u;
    }
    __shared__ int ws[8];
    if (lane == 31) ws[wid] = inc;
    __syncthreads();
    int wbase = 0;
#pragma unroll
    for (int w = 0; w < 8; ++w) wbase += (w < wid) ? ws[w] : 0;
    int excl = g_boff[blockIdx.x] + wbase + inc - v;
    if (i < NN) { g_off[i] = excl; g_cur[i] = excl; }
}

// ---------------- scatter (packed only) ----------------
__global__ void k_scatter(const int* __restrict__ src,
                          const int* __restrict__ dst,
                          const int* __restrict__ rel) {
    int e = blockIdx.x * blockDim.x + threadIdx.x;
    if (e >= EE) return;
    int s = src[e], d = dst[e], r = rel[e];
    int p = atomicAdd(&g_cur[d], 1);
    g_packed[p] = s | (r << 16);
}

// ---------------- fused online-softmax aggregation: 2 warps per node --------
__global__ __launch_bounds__(256) void k_agg(const float* __restrict__ coeff,
                                             float* __restrict__ out) {
    __shared__ __align__(16) float cf[CC * BB];      // cf[(r*4+h)*4 + b]
    __shared__ float s_mxdn[4][2][8];                // [node][sub][mx0-3,dn0-3]
    __shared__ float s_part[4][64];                  // warp B partial output
    int tid = threadIdx.x;
    if (tid < CC * BB) cf[tid] = coeff[tid];

    int lane = tid & 31, w = tid >> 5;
    int node = w >> 1;           // 0..3 within block
    int sub = w & 1;             // 0 = warp A, 1 = warp B
    int n = blockIdx.x * 4 + node;
    bool active = (n < NN);

    int beg = 0, end = 0;
    if (active) { beg = g_off[n]; end = g_off[n + 1]; }
    int len = end - beg;
    int half = (len + 1) >> 1;
    int mybeg = beg + (sub ? half : 0);
    int myend = sub ? end : (beg + half);

    __syncthreads();  // cf visible

    const float* kn = g_qk + n * 64 + 32;

    ull acc[4][2][2];  // [head][u-half][b-pair]
#pragma unroll
    for (int a = 0; a < 4; ++a)
#pragma unroll
        for (int hf = 0; hf < 2; ++hf) { acc[a][hf][0] = 0ull; acc[a][hf][1] = 0ull; }

    float mx[4], dn[4];
#pragma unroll
    for (int a = 0; a < 4; ++a) { mx[a] = __int_as_float(0xff800000); dn[a] = 0.f; }

    if (mybeg < myend) {
        int pk = g_packed[mybeg];
        for (int e = mybeg; e < myend; ++e) {
            int pkc = pk;
            if (e + 1 < myend) pk = g_packed[e + 1];

            int s = pkc & 0xFFFF, r = pkc >> 16;
            float4 q = *(const float4*)(g_qk + s * 64 + r * 4);
            float4 kk = *(const float4*)(kn + r * 4);
            float l[4];
            l[0] = q.x + kk.x; l[0] = l[0] > 0.f ? l[0] : 0.01f * l[0];
            l[1] = q.y + kk.y; l[1] = l[1] > 0.f ? l[1] : 0.01f * l[1];
            l[2] = q.z + kk.z; l[2] = l[2] > 0.f ? l[2] : 0.01f * l[2];
            l[3] = q.w + kk.w; l[3] = l[3] > 0.f ? l[3] : 0.01f * l[3];

            bool resc = false;
            float nmx[4];
#pragma unroll
            for (int a = 0; a < 4; ++a) {
                nmx[a] = fmaxf(mx[a], l[a]);
                resc |= (nmx[a] != mx[a]);
            }
            if (resc) {  // warp-uniform branch
#pragma unroll
                for (int a = 0; a < 4; ++a) {
                    float sc = __expf(mx[a] - nmx[a]);  // exp(-inf)=0 first edge
                    dn[a] *= sc;
                    ull sc2 = splat2(sc);
                    acc[a][0][0] = mul2(acc[a][0][0], sc2);
                    acc[a][0][1] = mul2(acc[a][0][1], sc2);
                    acc[a][1][0] = mul2(acc[a][1][0], sc2);
                    acc[a][1][1] = mul2(acc[a][1][1], sc2);
                    mx[a] = nmx[a];
                }
            }

            float wv[4];
#pragma unroll
            for (int a = 0; a < 4; ++a) {
                wv[a] = __expf(l[a] - mx[a]);
                dn[a] += wv[a];
            }

            const float4* yr = (const float4*)(g_y + (size_t)s * 256);
            float4 y0 = yr[lane];        // u = lane,    b0..b3
            float4 y1 = yr[32 + lane];   // u = lane+32, b0..b3
            ull y00 = pack2(y0.x, y0.y), y01 = pack2(y0.z, y0.w);
            ull y10 = pack2(y1.x, y1.y), y11 = pack2(y1.z, y1.w);
            const ull* cr = (const ull*)(cf + r * 16);
#pragma unroll
            for (int a = 0; a < 4; ++a) {
                ull wa = splat2(wv[a]);
                ull c0 = mul2(wa, cr[a * 2]);
                ull c1 = mul2(wa, cr[a * 2 + 1]);
                fma2(acc[a][0][0], c0, y00);
                fma2(acc[a][0][1], c1, y01);
                fma2(acc[a][1][0], c0, y10);
                fma2(acc[a][1][1], c1, y11);
            }
        }
    }

    // ---- exchange (mx, dn) between the warp pair ----
    if (lane == 0) {
        s_mxdn[node][sub][0] = mx[0]; s_mxdn[node][sub][1] = mx[1];
        s_mxdn[node][sub][2] = mx[2]; s_mxdn[node][sub][3] = mx[3];
        s_mxdn[node][sub][4] = dn[0]; s_mxdn[node][sub][5] = dn[1];
        s_mxdn[node][sub][6] = dn[2]; s_mxdn[node][sub][7] = dn[3];
    }
    __syncthreads();

    float o0 = 0.f, o1 = 0.f;
    if (active && len > 0) {
        const float* other = s_mxdn[node][1 - sub];
#pragma unroll
        for (int a = 0; a < 4; ++a) {
            float mo = other[a], dno = other[4 + a];
            float m = fmaxf(mx[a], mo);
            float eself = __expf(mx[a] - m);   // 0 if this half empty
            float eo = __expf(mo - m);
            float dt = dn[a] * eself + dno * eo;
            float scl = eself / fmaxf(dt, 1e-16f);
            float l0, h0, l1, h1, l2, h2, l3, h3;
            unpk2(l0, h0, acc[a][0][0]);
            unpk2(l1, h1, acc[a][0][1]);
            unpk2(l2, h2, acc[a][1][0]);
            unpk2(l3, h3, acc[a][1][1]);
            o0 += scl * ((l0 + h0) + (l1 + h1));
            o1 += scl * ((l2 + h2) + (l3 + h3));
        }
    }

    if (sub == 1) {
        s_part[node][lane] = o0;
        s_part[node][32 + lane] = o1;
    }
    __syncthreads();

    if (sub == 0 && active) {
        if (len == 0) {
            out[n * UU + lane] = 0.f;
            out[n * UU + 32 + lane] = 0.f;
        } else {
            o0 += s_part[node][lane];
            o1 += s_part[node][32 + lane];
            out[n * UU + lane] = 0.25f * o0;
            out[n * UU + 32 + lane] = 0.25f * o1;
        }
    }
}

// ---------------- launch (round-4/8 structure) ----------------
extern "C" void kernel_launch(void* const* d_in, const int* in_sizes, int n_in,
                              void* d_out, int out_size) {
    const float* x     = (const float*)d_in[0];
    const float* basis = (const float*)d_in[1];
    const float* coeff = (const float*)d_in[2];
    const float* aq    = (const float*)d_in[3];
    const float* ak    = (const float*)d_in[4];
    const int*   src   = (const int*)d_in[5];
    const int*   dst   = (const int*)d_in[6];
    const int*   rel   = (const int*)d_in[7];
    float* out = (float*)d_out;

    float* d_y;   cudaGetSymbolAddress((void**)&d_y, g_y);
    float* d_qk;  cudaGetSymbolAddress((void**)&d_qk, g_qk);
    float* d_wqk; cudaGetSymbolAddress((void**)&d_wqk, g_wqk);
    int*   d_deg; cudaGetSymbolAddress((void**)&d_deg, g_deg);

    cudaFuncSetAttribute(k_gemm, cudaFuncAttributeMaxDynamicSharedMemorySize, GEMM_SMEM);

    cudaStream_t s1 = 0, s2 = 0;
    bool fork = s_forkOK;
    if (fork) {
        s1 = s_s1; s2 = s_s2;
        cudaEventRecord(s_evRoot, 0);
        cudaStreamWaitEvent(s1, s_evRoot, 0);
        cudaStreamWaitEvent(s2, s_evRoot, 0);
    }

    // --- side stream 1: prep -> qk GEMM ---
    k_prep<<<32, 256, 0, s1>>>(coeff, basis, aq, ak);
    k_gemm<<<dim3((NN + GROWS - 1) / GROWS, 1), 256, GEMM_SMEM, s1>>>(
        x, d_wqk, d_qk, 64, 1, 0, 0, 0);

    // --- side stream 2: y GEMM ---
    k_gemm<<<dim3((NN + GROWS - 1) / GROWS, BB), 256, GEMM_SMEM, s2>>>(
        x, basis, d_y, 256, 4, 0, FF * UU, 1);

    if (fork) {
        cudaEventRecord(s_evA, s1);
        cudaEventRecord(s_evB, s2);
    }

    // --- main stream: counting sort ---
    cudaMemsetAsync(d_deg, 0, NN * sizeof(int), 0);
    k_hist<<<(EE / 4 + 255) / 256, 256>>>(dst);
    k_scanA<<<NBLK, 256>>>();
    k_scanB<<<1, 32>>>();
    k_scanC<<<NBLK, 256>>>();
    k_scatter<<<(EE + 255) / 256, 256>>>(src, dst, rel);

    if (fork) {
        cudaStreamWaitEvent(0, s_evA, 0);
        cudaStreamWaitEvent(0, s_evB, 0);
    }
    k_agg<<<(NN + 3) / 4, 256>>>(coeff, out);
}

// round 10
// speedup vs baseline: 2.8965x; 1.0276x over previous
#include <cuda_runtime.h>

#define NN 20000
#define FF 256
#define RR 8
#define HH 4
#define UU 64
#define BB 4
#define CC 32   // R*H
#define EE 320000
#define NBLK 79  // ceil(NN/256)

typedef unsigned long long ull;

// ---------------- f32x2 packed math helpers ----------------
__device__ __forceinline__ ull splat2(float v) {
    ull r; asm("mov.b64 %0, {%1, %1};" : "=l"(r) : "f"(v)); return r;
}
__device__ __forceinline__ ull pack2(float lo, float hi) {
    ull r; asm("mov.b64 %0, {%1, %2};" : "=l"(r) : "f"(lo), "f"(hi)); return r;
}
__device__ __forceinline__ void fma2(ull& d, ull a, ull b) {
    asm("fma.rn.f32x2 %0, %1, %2, %0;" : "+l"(d) : "l"(a), "l"(b));
}
__device__ __forceinline__ ull mul2(ull a, ull b) {
    ull d; asm("mul.rn.f32x2 %0, %1, %2;" : "=l"(d) : "l"(a), "l"(b)); return d;
}
__device__ __forceinline__ void unpk2(float& lo, float& hi, ull v) {
    asm("mov.b64 {%0, %1}, %2;" : "=f"(lo), "=f"(hi) : "l"(v));
}

// ---------------- device scratch ----------------
__device__ float  g_y[NN * BB * UU];   // y[n][u*4 + b]  (interleaved, 20.48 MB)
__device__ float  g_qk[NN * 64];       // [n][c] c<32: q(c=r*4+h), c>=32: k
__device__ float  g_wqk[FF * 64];      // [f][c] k-major weight for qk GEMM
__device__ int    g_deg[NN];
__device__ int    g_off[NN + 1];
__device__ int    g_cur[NN];
__device__ int    g_bsum[NBLK];
__device__ int    g_boff[NBLK];
__device__ int    g_packed[EE];        // src | (rel<<16), CSR-sorted by dst
__device__ float4 g_alpha[EE];         // per-CSR-slot: logit -> wexp per head
__device__ float4 g_inv[NN];           // per-node 1/denominator per head

// ---------------- static stream/event bootstrap ----------------
static cudaStream_t s_s1 = 0, s_s2 = 0;
static cudaEvent_t  s_evRoot = 0, s_evA = 0, s_evB = 0;
static bool s_forkOK = false;
namespace {
struct Boot {
    Boot() {
        bool ok = true;
        ok &= (cudaStreamCreateWithFlags(&s_s1, cudaStreamNonBlocking) == cudaSuccess);
        ok &= (cudaStreamCreateWithFlags(&s_s2, cudaStreamNonBlocking) == cudaSuccess);
        ok &= (cudaEventCreateWithFlags(&s_evRoot, cudaEventDisableTiming) == cudaSuccess);
        ok &= (cudaEventCreateWithFlags(&s_evA, cudaEventDisableTiming) == cudaSuccess);
        ok &= (cudaEventCreateWithFlags(&s_evB, cudaEventDisableTiming) == cudaSuccess);
        s_forkOK = ok;
    }
} s_boot;
}

// ---------------- K0: qk weight build (smem-staged, coalesced) ----------------
__global__ __launch_bounds__(256) void k_prep(const float* __restrict__ coeff,
                                              const float* __restrict__ basis,
                                              const float* __restrict__ aq,
                                              const float* __restrict__ ak) {
    __shared__ float bs[BB][8][UU + 1];
    __shared__ float aqs[CC][UU + 1];
    __shared__ float aks[CC][UU + 1];
    int t = threadIdx.x;
    int f_base = blockIdx.x * 8;

    for (int i = t; i < CC * UU; i += 256) {
        int c = i >> 6, u = i & 63;
        aqs[c][u] = aq[i];
        aks[c][u] = ak[i];
    }
    for (int i = t; i < BB * 8 * UU; i += 256) {
        int b = i >> 9;
        int rem = i & 511;
        int fl = rem >> 6, u = rem & 63;
        bs[b][fl][u] = basis[(b * FF + f_base + fl) * UU + u];
    }
    __syncthreads();

    int c = t >> 3, fl = t & 7;
    float sq = 0.f, sk = 0.f;
#pragma unroll
    for (int b = 0; b < BB; ++b) {
        float dq = 0.f, dk = 0.f;
        const float* bp = bs[b][fl];
        const float* aqc = aqs[c];
        const float* akc = aks[c];
#pragma unroll 8
        for (int u = 0; u < UU; ++u) {
            float bv = bp[u];
            dq += bv * aqc[u];
            dk += bv * akc[u];
        }
        float cb = coeff[c * BB + b];
        sq += cb * dq;
        sk += cb * dk;
    }
    int f = f_base + fl;
    g_wqk[f * 64 + c]      = sq;
    g_wqk[f * 64 + 32 + c] = sk;
}

// ---------------- K1: generic 128x64 FFMA2 GEMM ----------------
#define GROWS 128
#define KC 128
#define XPAD 132
#define GEMM_SMEM ((KC * XPAD + KC * 64) * 4)

__global__ __launch_bounds__(256, 2) void k_gemm(const float* __restrict__ x,
                                                 const float* __restrict__ w,
                                                 float* __restrict__ out,
                                                 int ostride, int cmul, int cadd0,
                                                 int bstride, int caddstep) {
    extern __shared__ float sm[];
    float* xs = sm;                 // [KC][XPAD] transposed x chunk
    float* ws = sm + KC * XPAD;     // [KC][64]
    int tid = threadIdx.x;
    int tx = tid & 15, ty = tid >> 4;
    int m0 = blockIdx.x * GROWS;
    const float* wb = w + (size_t)blockIdx.y * bstride;
    int cadd = cadd0 + blockIdx.y * caddstep;

    ull acc[4][4];
#pragma unroll
    for (int i = 0; i < 4; ++i)
#pragma unroll
        for (int j = 0; j < 4; ++j) acc[i][j] = 0ull;

    for (int kc = 0; kc < 2; ++kc) {
        if (kc) __syncthreads();
        const float4* w4 = (const float4*)(wb + kc * KC * 64);
        float4* ws4 = (float4*)ws;
        for (int i = tid; i < KC * 16; i += 256) ws4[i] = w4[i];
        const float4* x4 = (const float4*)x;
        for (int i = tid; i < GROWS * 32; i += 256) {
            int row = i >> 5, k4 = i & 31;
            int n = m0 + row;
            float4 v = make_float4(0.f, 0.f, 0.f, 0.f);
            if (n < NN) v = x4[n * 64 + kc * 32 + k4];
            xs[(k4 * 4 + 0) * XPAD + row] = v.x;
            xs[(k4 * 4 + 1) * XPAD + row] = v.y;
            xs[(k4 * 4 + 2) * XPAD + row] = v.z;
            xs[(k4 * 4 + 3) * XPAD + row] = v.w;
        }
        __syncthreads();

        const float* wp = ws + tx * 4;
        const float* xp = xs + ty * 8;
#pragma unroll 8
        for (int k = 0; k < KC; ++k) {
            float4 bv = *(const float4*)(wp + k * 64);
            const float* xr = xp + k * XPAD;
            ull a0 = *(const ull*)(xr);
            ull a1 = *(const ull*)(xr + 2);
            ull a2 = *(const ull*)(xr + 4);
            ull a3 = *(const ull*)(xr + 6);
            ull s0 = splat2(bv.x), s1 = splat2(bv.y),
                s2 = splat2(bv.z), s3 = splat2(bv.w);
            fma2(acc[0][0], a0, s0); fma2(acc[1][0], a1, s0);
            fma2(acc[2][0], a2, s0); fma2(acc[3][0], a3, s0);
            fma2(acc[0][1], a0, s1); fma2(acc[1][1], a1, s1);
            fma2(acc[2][1], a2, s1); fma2(acc[3][1], a3, s1);
            fma2(acc[0][2], a0, s2); fma2(acc[1][2], a1, s2);
            fma2(acc[2][2], a2, s2); fma2(acc[3][2], a3, s2);
            fma2(acc[0][3], a0, s3); fma2(acc[1][3], a1, s3);
            fma2(acc[2][3], a2, s3); fma2(acc[3][3], a3, s3);
        }
    }

    int col0 = tx * 4;
#pragma unroll
    for (int ip = 0; ip < 4; ++ip) {
        float lo[4], hi[4];
#pragma unroll
        for (int j = 0; j < 4; ++j) unpk2(lo[j], hi[j], acc[ip][j]);
        int n0 = m0 + ty * 8 + ip * 2;
        if (n0 < NN) {
            float* o = out + (size_t)n0 * ostride + cadd;
#pragma unroll
            for (int j = 0; j < 4; ++j) o[(col0 + j) * cmul] = lo[j];
        }
        if (n0 + 1 < NN) {
            float* o = out + (size_t)(n0 + 1) * ostride + cadd;
#pragma unroll
            for (int j = 0; j < 4; ++j) o[(col0 + j) * cmul] = hi[j];
        }
    }
}

// ---------------- counting sort: hist + 3-phase parallel scan ----------------
__global__ void k_hist(const int* __restrict__ dst) {
    int i = blockIdx.x * blockDim.x + threadIdx.x;
    if (i * 4 < EE) {
        int4 d4 = ((const int4*)dst)[i];
        atomicAdd(&g_deg[d4.x], 1);
        atomicAdd(&g_deg[d4.y], 1);
        atomicAdd(&g_deg[d4.z], 1);
        atomicAdd(&g_deg[d4.w], 1);
    }
}

__global__ void k_scanA() {   // per-block sums
    int i = blockIdx.x * 256 + threadIdx.x;
    int v = (i < NN) ? g_deg[i] : 0;
#pragma unroll
    for (int o = 16; o; o >>= 1) v += __shfl_xor_sync(0xffffffffu, v, o);
    __shared__ int ws[8];
    if ((threadIdx.x & 31) == 0) ws[threadIdx.x >> 5] = v;
    __syncthreads();
    if (threadIdx.x == 0) {
        int s = 0;
#pragma unroll
        for (int w = 0; w < 8; ++w) s += ws[w];
        g_bsum[blockIdx.x] = s;
    }
}

__global__ void k_scanB() {   // 1 warp scans NBLK block sums
    int lane = threadIdx.x;
    int carry = 0;
    for (int base = 0; base < NBLK; base += 32) {
        int i = base + lane;
        int v = (i < NBLK) ? g_bsum[i] : 0;
        int inc = v;
#pragma unroll
        for (int o = 1; o < 32; o <<= 1) {
            int u = __shfl_up_sync(0xffffffffu, inc, o);
            if (lane >= o) inc += u;
        }
        if (i < NBLK) g_boff[i] = carry + inc - v;
        carry += __shfl_sync(0xffffffffu, inc, 31);
    }
    if (lane == 0) g_off[NN] = EE;
}

__global__ void k_scanC() {   // local exclusive scan + base
    int t = threadIdx.x, lane = t & 31, wid = t >> 5;
    int i = blockIdx.x * 256 + t;
    int v = (i < NN) ? g_deg[i] : 0;
    int inc = v;
#pragma unroll
    for (int o = 1; o < 32; o <<= 1) {
        int u = __shfl_up_sync(0xffffffffu, inc, o);
        if (lane >= o) inc += u;
    }
    __shared__ int ws[8];
    if (lane == 31) ws[wid] = inc;
    __syncthreads();
    int wbase = 0;
#pragma unroll
    for (int w = 0; w < 8; ++w) wbase += (w < wid) ? ws[w] : 0;
    int excl = g_boff[blockIdx.x] + wbase + inc - v;
    if (i < NN) { g_off[i] = excl; g_cur[i] = excl; }
}

// ---------------- scatter + fused per-edge logits ----------------
__global__ void k_scatter_logit(const int* __restrict__ src,
                                const int* __restrict__ dst,
                                const int* __restrict__ rel) {
    int e = blockIdx.x * blockDim.x + threadIdx.x;
    if (e >= EE) return;
    int s = src[e], d = dst[e], r = rel[e];
    int p = atomicAdd(&g_cur[d], 1);
    g_packed[p] = s | (r << 16);
    float4 q = *(const float4*)(g_qk + s * 64 + r * 4);
    float4 k = *(const float4*)(g_qk + d * 64 + 32 + r * 4);
    float4 l;
    l.x = q.x + k.x; l.x = l.x > 0.f ? l.x : 0.01f * l.x;
    l.y = q.y + k.y; l.y = l.y > 0.f ? l.y : 0.01f * l.y;
    l.z = q.z + k.z; l.z = l.z > 0.f ? l.z : 0.01f * l.z;
    l.w = q.w + k.w; l.w = l.w > 0.f ? l.w : 0.01f * l.w;
    g_alpha[p] = l;
}

// ---------------- per-node softmax: max + exp + inv-denominator ----------
// warp per node; lane covers (eslot = lane>>2, h = lane&3); coalesced.
__global__ __launch_bounds__(256) void k_mxden() {
    int lane = threadIdx.x & 31, w = threadIdx.x >> 5;
    int n = blockIdx.x * 8 + w;
    if (n >= NN) return;
    int beg = g_off[n], end = g_off[n + 1];
    if (beg == end) return;

    const float* lg = (const float*)g_alpha;
    // pass 1: per-head max
    float mx = __int_as_float(0xff800000);
    for (int e0 = beg; e0 < end; e0 += 8) {
        int idx = e0 * 4 + lane;
        if (idx < end * 4) mx = fmaxf(mx, lg[idx]);
    }
    mx = fmaxf(mx, __shfl_xor_sync(0xffffffffu, mx, 4));
    mx = fmaxf(mx, __shfl_xor_sync(0xffffffffu, mx, 8));
    mx = fmaxf(mx, __shfl_xor_sync(0xffffffffu, mx, 16));

    // pass 2: unnormalized wexp stored in place; accumulate denominator
    float* lgw = (float*)g_alpha;
    float dsum = 0.f;
    for (int e0 = beg; e0 < end; e0 += 8) {
        int idx = e0 * 4 + lane;
        if (idx < end * 4) {
            float wv = __expf(lg[idx] - mx);
            lgw[idx] = wv;
            dsum += wv;
        }
    }
    dsum += __shfl_xor_sync(0xffffffffu, dsum, 4);
    dsum += __shfl_xor_sync(0xffffffffu, dsum, 8);
    dsum += __shfl_xor_sync(0xffffffffu, dsum, 16);
    if (lane < 4) {
        float inv = 1.f / fmaxf(dsum, 1e-16f);
        ((float*)&g_inv[n])[lane] = inv;
    }
}

// ---------------- aggregation: 2 warps/node, no exp/max in hot loop ---------
__global__ __launch_bounds__(256) void k_agg(const float* __restrict__ coeff,
                                             float* __restrict__ out) {
    __shared__ __align__(16) float cf[CC * BB];   // cf[(r*4+h)*4 + b]
    __shared__ float s_part[4][64];               // warp B partial output
    int tid = threadIdx.x;
    if (tid < CC * BB) cf[tid] = coeff[tid];

    int lane = tid & 31, w = tid >> 5;
    int node = w >> 1;           // 0..3 within block
    int sub = w & 1;             // 0 = warp A, 1 = warp B
    int n = blockIdx.x * 4 + node;
    bool active = (n < NN);

    int beg = 0, end = 0;
    if (active) { beg = g_off[n]; end = g_off[n + 1]; }
    int len = end - beg;
    int half = (len + 1) >> 1;
    int mybeg = beg + (sub ? half : 0);
    int myend = sub ? end : (beg + half);

    __syncthreads();  // cf visible

    ull acc[4][2][2];  // [head][u-half][b-pair]
#pragma unroll
    for (int a = 0; a < 4; ++a)
#pragma unroll
        for (int hf = 0; hf < 2; ++hf) { acc[a][hf][0] = 0ull; acc[a][hf][1] = 0ull; }

    if (mybeg < myend) {
        int pk = g_packed[mybeg];
        for (int e = mybeg; e < myend; ++e) {
            int pkc = pk;
            if (e + 1 < myend) pk = g_packed[e + 1];

            int s = pkc & 0xFFFF, r = pkc >> 16;
            float4 alc = g_alpha[e];     // uniform wexp per head
            const float4* yr = (const float4*)(g_y + (size_t)s * 256);
            float4 y0 = yr[lane];        // u = lane,    b0..b3
            float4 y1 = yr[32 + lane];   // u = lane+32, b0..b3
            ull y00 = pack2(y0.x, y0.y), y01 = pack2(y0.z, y0.w);
            ull y10 = pack2(y1.x, y1.y), y11 = pack2(y1.z, y1.w);
            const ull* cr = (const ull*)(cf + r * 16);
            float wv[4] = {alc.x, alc.y, alc.z, alc.w};
#pragma unroll
            for (int a = 0; a < 4; ++a) {
                ull wa = splat2(wv[a]);
                ull c0 = mul2(wa, cr[a * 2]);
                ull c1 = mul2(wa, cr[a * 2 + 1]);
                fma2(acc[a][0][0], c0, y00);
                fma2(acc[a][0][1], c1, y01);
                fma2(acc[a][1][0], c0, y10);
                fma2(acc[a][1][1], c1, y11);
            }
        }
    }

    float o0 = 0.f, o1 = 0.f;
    if (active && len > 0) {
        float4 iv = g_inv[n];
        float invs[4] = {iv.x, iv.y, iv.z, iv.w};
#pragma unroll
        for (int a = 0; a < 4; ++a) {
            float l0, h0, l1, h1, l2, h2, l3, h3;
            unpk2(l0, h0, acc[a][0][0]);
            unpk2(l1, h1, acc[a][0][1]);
            unpk2(l2, h2, acc[a][1][0]);
            unpk2(l3, h3, acc[a][1][1]);
            o0 += invs[a] * ((l0 + h0) + (l1 + h1));
            o1 += invs[a] * ((l2 + h2) + (l3 + h3));
        }
    }

    if (sub == 1) {
        s_part[node][lane] = o0;
        s_part[node][32 + lane] = o1;
    }
    __syncthreads();

    if (sub == 0 && active) {
        if (len == 0) {
            out[n * UU + lane] = 0.f;
            out[n * UU + 32 + lane] = 0.f;
        } else {
            o0 += s_part[node][lane];
            o1 += s_part[node][32 + lane];
            out[n * UU + lane] = 0.25f * o0;
            out[n * UU + 32 + lane] = 0.25f * o1;
        }
    }
}

// ---------------- launch ----------------
extern "C" void kernel_launch(void* const* d_in, const int* in_sizes, int n_in,
                              void* d_out, int out_size) {
    const float* x     = (const float*)d_in[0];
    const float* basis = (const float*)d_in[1];
    const float* coeff = (const float*)d_in[2];
    const float* aq    = (const float*)d_in[3];
    const float* ak    = (const float*)d_in[4];
    const int*   src   = (const int*)d_in[5];
    const int*   dst   = (const int*)d_in[6];
    const int*   rel   = (const int*)d_in[7];
    float* out = (float*)d_out;

    float* d_y;   cudaGetSymbolAddress((void**)&d_y, g_y);
    float* d_qk;  cudaGetSymbolAddress((void**)&d_qk, g_qk);
    float* d_wqk; cudaGetSymbolAddress((void**)&d_wqk, g_wqk);
    int*   d_deg; cudaGetSymbolAddress((void**)&d_deg, g_deg);

    cudaFuncSetAttribute(k_gemm, cudaFuncAttributeMaxDynamicSharedMemorySize, GEMM_SMEM);

    cudaStream_t s1 = 0, s2 = 0;
    bool fork = s_forkOK;
    if (fork) {
        s1 = s_s1; s2 = s_s2;
        cudaEventRecord(s_evRoot, 0);
        cudaStreamWaitEvent(s1, s_evRoot, 0);
        cudaStreamWaitEvent(s2, s_evRoot, 0);
    }

    // --- side stream 1: prep -> qk GEMM ---
    k_prep<<<32, 256, 0, s1>>>(coeff, basis, aq, ak);
    k_gemm<<<dim3((NN + GROWS - 1) / GROWS, 1), 256, GEMM_SMEM, s1>>>(
        x, d_wqk, d_qk, 64, 1, 0, 0, 0);

    // --- side stream 2: y GEMM ---
    k_gemm<<<dim3((NN + GROWS - 1) / GROWS, BB), 256, GEMM_SMEM, s2>>>(
        x, basis, d_y, 256, 4, 0, FF * UU, 1);

    if (fork) {
        cudaEventRecord(s_evA, s1);
        cudaEventRecord(s_evB, s2);
    }

    // --- main stream: counting sort ---
    cudaMemsetAsync(d_deg, 0, NN * sizeof(int), 0);
    k_hist<<<(EE / 4 + 255) / 256, 256>>>(dst);
    k_scanA<<<NBLK, 256>>>();
    k_scanB<<<1, 32>>>();
    k_scanC<<<NBLK, 256>>>();

    // scatter_logit reads g_qk -> must wait for qk GEMM
    if (fork) cudaStreamWaitEvent(0, s_evA, 0);
    k_scatter_logit<<<(EE + 255) / 256, 256>>>(src, dst, rel);
    k_mxden<<<(NN + 7) / 8, 256>>>();

    if (fork) cudaStreamWaitEvent(0, s_evB, 0);
    k_agg<<<(NN + 3) / 4, 256>>>(coeff, out);
}

// round 11
// speedup vs baseline: 3.2641x; 1.1269x over previous
#include <cuda_runtime.h>

#define NN 20000
#define FF 256
#define RR 8
#define HH 4
#define UU 64
#define BB 4
#define CC 32   // R*H
#define EE 320000
#define NBLK 79  // ceil(NN/256)

typedef unsigned long long ull;

// ---------------- f32x2 packed math helpers ----------------
__device__ __forceinline__ ull splat2(float v) {
    ull r; asm("mov.b64 %0, {%1, %1};" : "=l"(r) : "f"(v)); return r;
}
__device__ __forceinline__ ull pack2(float lo, float hi) {
    ull r; asm("mov.b64 %0, {%1, %2};" : "=l"(r) : "f"(lo), "f"(hi)); return r;
}
__device__ __forceinline__ void fma2(ull& d, ull a, ull b) {
    asm("fma.rn.f32x2 %0, %1, %2, %0;" : "+l"(d) : "l"(a), "l"(b));
}
__device__ __forceinline__ ull mul2(ull a, ull b) {
    ull d; asm("mul.rn.f32x2 %0, %1, %2;" : "=l"(d) : "l"(a), "l"(b)); return d;
}
__device__ __forceinline__ void unpk2(float& lo, float& hi, ull v) {
    asm("mov.b64 {%0, %1}, %2;" : "=f"(lo), "=f"(hi) : "l"(v));
}

// ---------------- device scratch ----------------
__device__ float  g_y[NN * BB * UU];   // y[n][u*4 + b]  (interleaved, 20.48 MB)
__device__ float  g_qk[NN * 64];       // [n][c] c<32: q(c=r*4+h), c>=32: k
__device__ float  g_wqk[FF * 64];      // [f][c] k-major weight for qk GEMM
__device__ int    g_deg[NN];
__device__ int    g_off[NN + 1];
__device__ int    g_cur[NN];
__device__ int    g_bsum[NBLK];
__device__ int    g_boff[NBLK];
__device__ int    g_packed[EE];        // src | (rel<<16), CSR-sorted by dst
__device__ float4 g_alpha[EE];         // per-CSR-slot: logit -> wexp per head
__device__ float4 g_beta[EE];          // per-CSR-slot: head-folded weights per b

// ---------------- static stream/event bootstrap ----------------
static cudaStream_t s_s1 = 0, s_s2 = 0;
static cudaEvent_t  s_evRoot = 0, s_evA = 0, s_evB = 0;
static bool s_forkOK = false;
namespace {
struct Boot {
    Boot() {
        bool ok = true;
        ok &= (cudaStreamCreateWithFlags(&s_s1, cudaStreamNonBlocking) == cudaSuccess);
        ok &= (cudaStreamCreateWithFlags(&s_s2, cudaStreamNonBlocking) == cudaSuccess);
        ok &= (cudaEventCreateWithFlags(&s_evRoot, cudaEventDisableTiming) == cudaSuccess);
        ok &= (cudaEventCreateWithFlags(&s_evA, cudaEventDisableTiming) == cudaSuccess);
        ok &= (cudaEventCreateWithFlags(&s_evB, cudaEventDisableTiming) == cudaSuccess);
        s_forkOK = ok;
    }
} s_boot;
}

// ---------------- K0: qk weight build (smem-staged, coalesced) ----------------
__global__ __launch_bounds__(256) void k_prep(const float* __restrict__ coeff,
                                              const float* __restrict__ basis,
                                              const float* __restrict__ aq,
                                              const float* __restrict__ ak) {
    __shared__ float bs[BB][8][UU + 1];
    __shared__ float aqs[CC][UU + 1];
    __shared__ float aks[CC][UU + 1];
    int t = threadIdx.x;
    int f_base = blockIdx.x * 8;

    for (int i = t; i < CC * UU; i += 256) {
        int c = i >> 6, u = i & 63;
        aqs[c][u] = aq[i];
        aks[c][u] = ak[i];
    }
    for (int i = t; i < BB * 8 * UU; i += 256) {
        int b = i >> 9;
        int rem = i & 511;
        int fl = rem >> 6, u = rem & 63;
        bs[b][fl][u] = basis[(b * FF + f_base + fl) * UU + u];
    }
    __syncthreads();

    int c = t >> 3, fl = t & 7;
    float sq = 0.f, sk = 0.f;
#pragma unroll
    for (int b = 0; b < BB; ++b) {
        float dq = 0.f, dk = 0.f;
        const float* bp = bs[b][fl];
        const float* aqc = aqs[c];
        const float* akc = aks[c];
#pragma unroll 8
        for (int u = 0; u < UU; ++u) {
            float bv = bp[u];
            dq += bv * aqc[u];
            dk += bv * akc[u];
        }
        float cb = coeff[c * BB + b];
        sq += cb * dq;
        sk += cb * dk;
    }
    int f = f_base + fl;
    g_wqk[f * 64 + c]      = sq;
    g_wqk[f * 64 + 32 + c] = sk;
}

// ---------------- K1: generic 128x64 FFMA2 GEMM ----------------
#define GROWS 128
#define KC 128
#define XPAD 132
#define GEMM_SMEM ((KC * XPAD + KC * 64) * 4)

__global__ __launch_bounds__(256, 2) void k_gemm(const float* __restrict__ x,
                                                 const float* __restrict__ w,
                                                 float* __restrict__ out,
                                                 int ostride, int cmul, int cadd0,
                                                 int bstride, int caddstep) {
    extern __shared__ float sm[];
    float* xs = sm;                 // [KC][XPAD] transposed x chunk
    float* ws = sm + KC * XPAD;     // [KC][64]
    int tid = threadIdx.x;
    int tx = tid & 15, ty = tid >> 4;
    int m0 = blockIdx.x * GROWS;
    const float* wb = w + (size_t)blockIdx.y * bstride;
    int cadd = cadd0 + blockIdx.y * caddstep;

    ull acc[4][4];
#pragma unroll
    for (int i = 0; i < 4; ++i)
#pragma unroll
        for (int j = 0; j < 4; ++j) acc[i][j] = 0ull;

    for (int kc = 0; kc < 2; ++kc) {
        if (kc) __syncthreads();
        const float4* w4 = (const float4*)(wb + kc * KC * 64);
        float4* ws4 = (float4*)ws;
        for (int i = tid; i < KC * 16; i += 256) ws4[i] = w4[i];
        const float4* x4 = (const float4*)x;
        for (int i = tid; i < GROWS * 32; i += 256) {
            int row = i >> 5, k4 = i & 31;
            int n = m0 + row;
            float4 v = make_float4(0.f, 0.f, 0.f, 0.f);
            if (n < NN) v = x4[n * 64 + kc * 32 + k4];
            xs[(k4 * 4 + 0) * XPAD + row] = v.x;
            xs[(k4 * 4 + 1) * XPAD + row] = v.y;
            xs[(k4 * 4 + 2) * XPAD + row] = v.z;
            xs[(k4 * 4 + 3) * XPAD + row] = v.w;
        }
        __syncthreads();

        const float* wp = ws + tx * 4;
        const float* xp = xs + ty * 8;
#pragma unroll 8
        for (int k = 0; k < KC; ++k) {
            float4 bv = *(const float4*)(wp + k * 64);
            const float* xr = xp + k * XPAD;
            ull a0 = *(const ull*)(xr);
            ull a1 = *(const ull*)(xr + 2);
            ull a2 = *(const ull*)(xr + 4);
            ull a3 = *(const ull*)(xr + 6);
            ull s0 = splat2(bv.x), s1 = splat2(bv.y),
                s2 = splat2(bv.z), s3 = splat2(bv.w);
            fma2(acc[0][0], a0, s0); fma2(acc[1][0], a1, s0);
            fma2(acc[2][0], a2, s0); fma2(acc[3][0], a3, s0);
            fma2(acc[0][1], a0, s1); fma2(acc[1][1], a1, s1);
            fma2(acc[2][1], a2, s1); fma2(acc[3][1], a3, s1);
            fma2(acc[0][2], a0, s2); fma2(acc[1][2], a1, s2);
            fma2(acc[2][2], a2, s2); fma2(acc[3][2], a3, s2);
            fma2(acc[0][3], a0, s3); fma2(acc[1][3], a1, s3);
            fma2(acc[2][3], a2, s3); fma2(acc[3][3], a3, s3);
        }
    }

    int col0 = tx * 4;
#pragma unroll
    for (int ip = 0; ip < 4; ++ip) {
        float lo[4], hi[4];
#pragma unroll
        for (int j = 0; j < 4; ++j) unpk2(lo[j], hi[j], acc[ip][j]);
        int n0 = m0 + ty * 8 + ip * 2;
        if (n0 < NN) {
            float* o = out + (size_t)n0 * ostride + cadd;
#pragma unroll
            for (int j = 0; j < 4; ++j) o[(col0 + j) * cmul] = lo[j];
        }
        if (n0 + 1 < NN) {
            float* o = out + (size_t)(n0 + 1) * ostride + cadd;
#pragma unroll
            for (int j = 0; j < 4; ++j) o[(col0 + j) * cmul] = hi[j];
        }
    }
}

// ---------------- counting sort: hist + 3-phase parallel scan ----------------
__global__ void k_hist(const int* __restrict__ dst) {
    int i = blockIdx.x * blockDim.x + threadIdx.x;
    if (i * 4 < EE) {
        int4 d4 = ((const int4*)dst)[i];
        atomicAdd(&g_deg[d4.x], 1);
        atomicAdd(&g_deg[d4.y], 1);
        atomicAdd(&g_deg[d4.z], 1);
        atomicAdd(&g_deg[d4.w], 1);
    }
}

__global__ void k_scanA() {   // per-block sums
    int i = blockIdx.x * 256 + threadIdx.x;
    int v = (i < NN) ? g_deg[i] : 0;
#pragma unroll
    for (int o = 16; o; o >>= 1) v += __shfl_xor_sync(0xffffffffu, v, o);
    __shared__ int ws[8];
    if ((threadIdx.x & 31) == 0) ws[threadIdx.x >> 5] = v;
    __syncthreads();
    if (threadIdx.x == 0) {
        int s = 0;
#pragma unroll
        for (int w = 0; w < 8; ++w) s += ws[w];
        g_bsum[blockIdx.x] = s;
    }
}

__global__ void k_scanB() {   // 1 warp scans NBLK block sums
    int lane = threadIdx.x;
    int carry = 0;
    for (int base = 0; base < NBLK; base += 32) {
        int i = base + lane;
        int v = (i < NBLK) ? g_bsum[i] : 0;
        int inc = v;
#pragma unroll
        for (int o = 1; o < 32; o <<= 1) {
            int u = __shfl_up_sync(0xffffffffu, inc, o);
            if (lane >= o) inc += u;
        }
        if (i < NBLK) g_boff[i] = carry + inc - v;
        carry += __shfl_sync(0xffffffffu, inc, 31);
    }
    if (lane == 0) g_off[NN] = EE;
}

__global__ void k_scanC() {   // local exclusive scan + base
    int t = threadIdx.x, lane = t & 31, wid = t >> 5;
    int i = blockIdx.x * 256 + t;
    int v = (i < NN) ? g_deg[i] : 0;
    int inc = v;
#pragma unroll
    for (int o = 1; o < 32; o <<= 1) {
        int u = __shfl_up_sync(0xffffffffu, inc, o);
        if (lane >= o) inc += u;
    }
    __shared__ int ws[8];
    if (lane == 31) ws[wid] = inc;
    __syncthreads();
    int wbase = 0;
#pragma unroll
    for (int w = 0; w < 8; ++w) wbase += (w < wid) ? ws[w] : 0;
    int excl = g_boff[blockIdx.x] + wbase + inc - v;
    if (i < NN) { g_off[i] = excl; g_cur[i] = excl; }
}

// ---------------- scatter + fused per-edge logits ----------------
__global__ void k_scatter_logit(const int* __restrict__ src,
                                const int* __restrict__ dst,
                                const int* __restrict__ rel) {
    int e = blockIdx.x * blockDim.x + threadIdx.x;
    if (e >= EE) return;
    int s = src[e], d = dst[e], r = rel[e];
    int p = atomicAdd(&g_cur[d], 1);
    g_packed[p] = s | (r << 16);
    float4 q = *(const float4*)(g_qk + s * 64 + r * 4);
    float4 k = *(const float4*)(g_qk + d * 64 + 32 + r * 4);
    float4 l;
    l.x = q.x + k.x; l.x = l.x > 0.f ? l.x : 0.01f * l.x;
    l.y = q.y + k.y; l.y = l.y > 0.f ? l.y : 0.01f * l.y;
    l.z = q.z + k.z; l.z = l.z > 0.f ? l.z : 0.01f * l.z;
    l.w = q.w + k.w; l.w = l.w > 0.f ? l.w : 0.01f * l.w;
    g_alpha[p] = l;
}

// ---------------- per-node softmax + head-folded edge weights ----------
// warp per node. Pass 1: per-head max. Pass 2: wexp + denominator.
// Pass 3: beta_e[b] = sum_h inv_h * wexp_{e,h} * c[r,h,b]  (4 lanes/edge).
__global__ __launch_bounds__(256) void k_mxden(const float* __restrict__ coeff) {
    __shared__ __align__(16) float cf[CC * BB];   // cf[(r*4+h)*4 + b]
    int tid = threadIdx.x;
    if (tid < CC * BB) cf[tid] = coeff[tid];
    __syncthreads();

    int lane = tid & 31, w = tid >> 5;
    int n = blockIdx.x * 8 + w;
    if (n >= NN) return;
    int beg = g_off[n], end = g_off[n + 1];
    if (beg == end) return;

    const float* lg = (const float*)g_alpha;
    // pass 1: per-head max (lane covers eslot=lane>>2, h=lane&3)
    float mx = __int_as_float(0xff800000);
    for (int e0 = beg; e0 < end; e0 += 8) {
        int idx = e0 * 4 + lane;
        if (idx < end * 4) mx = fmaxf(mx, lg[idx]);
    }
    mx = fmaxf(mx, __shfl_xor_sync(0xffffffffu, mx, 4));
    mx = fmaxf(mx, __shfl_xor_sync(0xffffffffu, mx, 8));
    mx = fmaxf(mx, __shfl_xor_sync(0xffffffffu, mx, 16));

    // pass 2: unnormalized wexp stored in place; accumulate denominator
    float* lgw = (float*)g_alpha;
    float dsum = 0.f;
    for (int e0 = beg; e0 < end; e0 += 8) {
        int idx = e0 * 4 + lane;
        if (idx < end * 4) {
            float wv = __expf(lg[idx] - mx);
            lgw[idx] = wv;
            dsum += wv;
        }
    }
    dsum += __shfl_xor_sync(0xffffffffu, dsum, 4);
    dsum += __shfl_xor_sync(0xffffffffu, dsum, 8);
    dsum += __shfl_xor_sync(0xffffffffu, dsum, 16);
    // every lane holds its own h-class denominator; gather all 4 invs
    float inv_self = 1.f / fmaxf(dsum, 1e-16f);
    float inv0 = __shfl_sync(0xffffffffu, inv_self, 0);
    float inv1 = __shfl_sync(0xffffffffu, inv_self, 1);
    float inv2 = __shfl_sync(0xffffffffu, inv_self, 2);
    float inv3 = __shfl_sync(0xffffffffu, inv_self, 3);

    // pass 3: beta. 4 lanes per edge, b = lane&3; coalesced write.
    float* bt = (float*)g_beta;
    for (int e0 = beg; e0 < end; e0 += 8) {
        int idx = e0 * 4 + lane;
        if (idx < end * 4) {
            int e = idx >> 2, b = idx & 3;
            int r = g_packed[e] >> 16;
            float w0 = lgw[e * 4 + 0];
            float w1 = lgw[e * 4 + 1];
            float w2 = lgw[e * 4 + 2];
            float w3 = lgw[e * 4 + 3];
            const float* cr = cf + r * 16;
            float bv = inv0 * w0 * cr[b]
                     + inv1 * w1 * cr[4 + b]
                     + inv2 * w2 * cr[8 + b]
                     + inv3 * w3 * cr[12 + b];
            bt[idx] = bv;
        }
    }
}

// ---------------- aggregation: head-free, 4 accumulators, 2 warps/node ------
__global__ __launch_bounds__(256) void k_agg(float* __restrict__ out) {
    __shared__ float s_part[4][64];               // warp B partial output
    int tid = threadIdx.x;
    int lane = tid & 31, w = tid >> 5;
    int node = w >> 1;           // 0..3 within block
    int sub = w & 1;             // 0 = warp A, 1 = warp B
    int n = blockIdx.x * 4 + node;
    bool active = (n < NN);

    int beg = 0, end = 0;
    if (active) { beg = g_off[n]; end = g_off[n + 1]; }
    int len = end - beg;
    int half = (len + 1) >> 1;
    int mybeg = beg + (sub ? half : 0);
    int myend = sub ? end : (beg + half);

    ull acc00 = 0ull, acc01 = 0ull, acc10 = 0ull, acc11 = 0ull;

    if (mybeg < myend) {
        int pk = g_packed[mybeg];
        for (int e = mybeg; e < myend; ++e) {
            int pkc = pk;
            if (e + 1 < myend) pk = g_packed[e + 1];

            int s = pkc & 0xFFFF;
            float4 bt = g_beta[e];       // uniform per warp
            const float4* yr = (const float4*)(g_y + (size_t)s * 256);
            float4 y0 = yr[lane];        // u = lane,    b0..b3
            float4 y1 = yr[32 + lane];   // u = lane+32, b0..b3
            ull b01 = pack2(bt.x, bt.y);
            ull b23 = pack2(bt.z, bt.w);
            fma2(acc00, b01, pack2(y0.x, y0.y));
            fma2(acc01, b23, pack2(y0.z, y0.w));
            fma2(acc10, b01, pack2(y1.x, y1.y));
            fma2(acc11, b23, pack2(y1.z, y1.w));
        }
    }

    float o0 = 0.f, o1 = 0.f;
    {
        float l0, h0, l1, h1, l2, h2, l3, h3;
        unpk2(l0, h0, acc00);
        unpk2(l1, h1, acc01);
        unpk2(l2, h2, acc10);
        unpk2(l3, h3, acc11);
        o0 = (l0 + h0) + (l1 + h1);
        o1 = (l2 + h2) + (l3 + h3);
    }

    if (sub == 1) {
        s_part[node][lane] = o0;
        s_part[node][32 + lane] = o1;
    }
    __syncthreads();

    if (sub == 0 && active) {
        o0 += s_part[node][lane];
        o1 += s_part[node][32 + lane];
        out[n * UU + lane] = 0.25f * o0;
        out[n * UU + 32 + lane] = 0.25f * o1;
    }
}

// ---------------- launch ----------------
extern "C" void kernel_launch(void* const* d_in, const int* in_sizes, int n_in,
                              void* d_out, int out_size) {
    const float* x     = (const float*)d_in[0];
    const float* basis = (const float*)d_in[1];
    const float* coeff = (const float*)d_in[2];
    const float* aq    = (const float*)d_in[3];
    const float* ak    = (const float*)d_in[4];
    const int*   src   = (const int*)d_in[5];
    const int*   dst   = (const int*)d_in[6];
    const int*   rel   = (const int*)d_in[7];
    float* out = (float*)d_out;

    float* d_y;   cudaGetSymbolAddress((void**)&d_y, g_y);
    float* d_qk;  cudaGetSymbolAddress((void**)&d_qk, g_qk);
    float* d_wqk; cudaGetSymbolAddress((void**)&d_wqk, g_wqk);
    int*   d_deg; cudaGetSymbolAddress((void**)&d_deg, g_deg);

    cudaFuncSetAttribute(k_gemm, cudaFuncAttributeMaxDynamicSharedMemorySize, GEMM_SMEM);

    cudaStream_t s1 = 0, s2 = 0;
    bool fork = s_forkOK;
    if (fork) {
        s1 = s_s1; s2 = s_s2;
        cudaEventRecord(s_evRoot, 0);
        cudaStreamWaitEvent(s1, s_evRoot, 0);
        cudaStreamWaitEvent(s2, s_evRoot, 0);
    }

    // --- side stream 1: prep -> qk GEMM ---
    k_prep<<<32, 256, 0, s1>>>(coeff, basis, aq, ak);
    k_gemm<<<dim3((NN + GROWS - 1) / GROWS, 1), 256, GEMM_SMEM, s1>>>(
        x, d_wqk, d_qk, 64, 1, 0, 0, 0);

    // --- side stream 2: y GEMM ---
    k_gemm<<<dim3((NN + GROWS - 1) / GROWS, BB), 256, GEMM_SMEM, s2>>>(
        x, basis, d_y, 256, 4, 0, FF * UU, 1);

    if (fork) {
        cudaEventRecord(s_evA, s1);
        cudaEventRecord(s_evB, s2);
    }

    // --- main stream: counting sort ---
    cudaMemsetAsync(d_deg, 0, NN * sizeof(int), 0);
    k_hist<<<(EE / 4 + 255) / 256, 256>>>(dst);
    k_scanA<<<NBLK, 256>>>();
    k_scanB<<<1, 32>>>();
    k_scanC<<<NBLK, 256>>>();

    // scatter_logit reads g_qk -> must wait for qk GEMM
    if (fork) cudaStreamWaitEvent(0, s_evA, 0);
    k_scatter_logit<<<(EE + 255) / 256, 256>>>(src, dst, rel);
    k_mxden<<<(NN + 7) / 8, 256>>>(coeff);

    if (fork) cudaStreamWaitEvent(0, s_evB, 0);
    k_agg<<<(NN + 3) / 4, 256>>>(out);
}

// round 12
// speedup vs baseline: 3.5266x; 1.0804x over previous
#include <cuda_runtime.h>

#define NN 20000
#define FF 256
#define RR 8
#define HH 4
#define UU 64
#define BB 4
#define CC 32   // R*H
#define EE 320000
#define NBLK 79  // ceil(NN/256)

typedef unsigned long long ull;

// ---------------- f32x2 packed math helpers ----------------
__device__ __forceinline__ ull splat2(float v) {
    ull r; asm("mov.b64 %0, {%1, %1};" : "=l"(r) : "f"(v)); return r;
}
__device__ __forceinline__ ull pack2(float lo, float hi) {
    ull r; asm("mov.b64 %0, {%1, %2};" : "=l"(r) : "f"(lo), "f"(hi)); return r;
}
__device__ __forceinline__ void fma2(ull& d, ull a, ull b) {
    asm("fma.rn.f32x2 %0, %1, %2, %0;" : "+l"(d) : "l"(a), "l"(b));
}
__device__ __forceinline__ ull mul2(ull a, ull b) {
    ull d; asm("mul.rn.f32x2 %0, %1, %2;" : "=l"(d) : "l"(a), "l"(b)); return d;
}
__device__ __forceinline__ void unpk2(float& lo, float& hi, ull v) {
    asm("mov.b64 {%0, %1}, %2;" : "=f"(lo), "=f"(hi) : "l"(v));
}

// ---------------- device scratch ----------------
__device__ float  g_y[NN * BB * UU];   // y[n][u*4 + b]  (interleaved, 20.48 MB)
__device__ float  g_qk[NN * 64];       // [n][c] c<32: q(c=r*4+h), c>=32: k
__device__ float  g_wqk[FF * 64];      // [f][c] k-major weight for qk GEMM
__device__ int    g_deg[NN];           // zero at init; re-zeroed by k_scan
__device__ int    g_off[NN + 1];
__device__ int    g_cur[NN];
__device__ int    g_bsum[NBLK];        // 0 = not ready; -(sum+1) = ready. reset by k_scatter
__device__ int    g_packed[EE];        // src | (rel<<16), CSR-sorted by dst
__device__ float4 g_alpha[EE];         // per-CSR-slot: logit -> wexp per head
__device__ float4 g_beta[EE];          // per-CSR-slot: head-folded weights per b

// ---------------- static stream/event bootstrap ----------------
static cudaStream_t s_s1 = 0, s_s2 = 0;
static cudaEvent_t  s_evRoot = 0, s_evA = 0, s_evB = 0;
static bool s_forkOK = false;
namespace {
struct Boot {
    Boot() {
        bool ok = true;
        ok &= (cudaStreamCreateWithFlags(&s_s1, cudaStreamNonBlocking) == cudaSuccess);
        ok &= (cudaStreamCreateWithFlags(&s_s2, cudaStreamNonBlocking) == cudaSuccess);
        ok &= (cudaEventCreateWithFlags(&s_evRoot, cudaEventDisableTiming) == cudaSuccess);
        ok &= (cudaEventCreateWithFlags(&s_evA, cudaEventDisableTiming) == cudaSuccess);
        ok &= (cudaEventCreateWithFlags(&s_evB, cudaEventDisableTiming) == cudaSuccess);
        s_forkOK = ok;
    }
} s_boot;
}

// ---------------- K0: qk weight build (smem-staged, coalesced) ----------------
__global__ __launch_bounds__(256) void k_prep(const float* __restrict__ coeff,
                                              const float* __restrict__ basis,
                                              const float* __restrict__ aq,
                                              const float* __restrict__ ak) {
    __shared__ float bs[BB][8][UU + 1];
    __shared__ float aqs[CC][UU + 1];
    __shared__ float aks[CC][UU + 1];
    int t = threadIdx.x;
    int f_base = blockIdx.x * 8;

    for (int i = t; i < CC * UU; i += 256) {
        int c = i >> 6, u = i & 63;
        aqs[c][u] = aq[i];
        aks[c][u] = ak[i];
    }
    for (int i = t; i < BB * 8 * UU; i += 256) {
        int b = i >> 9;
        int rem = i & 511;
        int fl = rem >> 6, u = rem & 63;
        bs[b][fl][u] = basis[(b * FF + f_base + fl) * UU + u];
    }
    __syncthreads();

    int c = t >> 3, fl = t & 7;
    float sq = 0.f, sk = 0.f;
#pragma unroll
    for (int b = 0; b < BB; ++b) {
        float dq = 0.f, dk = 0.f;
        const float* bp = bs[b][fl];
        const float* aqc = aqs[c];
        const float* akc = aks[c];
#pragma unroll 8
        for (int u = 0; u < UU; ++u) {
            float bv = bp[u];
            dq += bv * aqc[u];
            dk += bv * akc[u];
        }
        float cb = coeff[c * BB + b];
        sq += cb * dq;
        sk += cb * dk;
    }
    int f = f_base + fl;
    g_wqk[f * 64 + c]      = sq;
    g_wqk[f * 64 + 32 + c] = sk;
}

// ---------------- K1: generic 128x64 FFMA2 GEMM ----------------
#define GROWS 128
#define KC 128
#define XPAD 132
#define GEMM_SMEM ((KC * XPAD + KC * 64) * 4)

__global__ __launch_bounds__(256, 2) void k_gemm(const float* __restrict__ x,
                                                 const float* __restrict__ w,
                                                 float* __restrict__ out,
                                                 int ostride, int cmul, int cadd0,
                                                 int bstride, int caddstep) {
    extern __shared__ float sm[];
    float* xs = sm;                 // [KC][XPAD] transposed x chunk
    float* ws = sm + KC * XPAD;     // [KC][64]
    int tid = threadIdx.x;
    int tx = tid & 15, ty = tid >> 4;
    int m0 = blockIdx.x * GROWS;
    const float* wb = w + (size_t)blockIdx.y * bstride;
    int cadd = cadd0 + blockIdx.y * caddstep;

    ull acc[4][4];
#pragma unroll
    for (int i = 0; i < 4; ++i)
#pragma unroll
        for (int j = 0; j < 4; ++j) acc[i][j] = 0ull;

    for (int kc = 0; kc < 2; ++kc) {
        if (kc) __syncthreads();
        const float4* w4 = (const float4*)(wb + kc * KC * 64);
        float4* ws4 = (float4*)ws;
        for (int i = tid; i < KC * 16; i += 256) ws4[i] = w4[i];
        const float4* x4 = (const float4*)x;
        for (int i = tid; i < GROWS * 32; i += 256) {
            int row = i >> 5, k4 = i & 31;
            int n = m0 + row;
            float4 v = make_float4(0.f, 0.f, 0.f, 0.f);
            if (n < NN) v = x4[n * 64 + kc * 32 + k4];
            xs[(k4 * 4 + 0) * XPAD + row] = v.x;
            xs[(k4 * 4 + 1) * XPAD + row] = v.y;
            xs[(k4 * 4 + 2) * XPAD + row] = v.z;
            xs[(k4 * 4 + 3) * XPAD + row] = v.w;
        }
        __syncthreads();

        const float* wp = ws + tx * 4;
        const float* xp = xs + ty * 8;
#pragma unroll 8
        for (int k = 0; k < KC; ++k) {
            float4 bv = *(const float4*)(wp + k * 64);
            const float* xr = xp + k * XPAD;
            ull a0 = *(const ull*)(xr);
            ull a1 = *(const ull*)(xr + 2);
            ull a2 = *(const ull*)(xr + 4);
            ull a3 = *(const ull*)(xr + 6);
            ull s0 = splat2(bv.x), s1 = splat2(bv.y),
                s2 = splat2(bv.z), s3 = splat2(bv.w);
            fma2(acc[0][0], a0, s0); fma2(acc[1][0], a1, s0);
            fma2(acc[2][0], a2, s0); fma2(acc[3][0], a3, s0);
            fma2(acc[0][1], a0, s1); fma2(acc[1][1], a1, s1);
            fma2(acc[2][1], a2, s1); fma2(acc[3][1], a3, s1);
            fma2(acc[0][2], a0, s2); fma2(acc[1][2], a1, s2);
            fma2(acc[2][2], a2, s2); fma2(acc[3][2], a3, s2);
            fma2(acc[0][3], a0, s3); fma2(acc[1][3], a1, s3);
            fma2(acc[2][3], a2, s3); fma2(acc[3][3], a3, s3);
        }
    }

    int col0 = tx * 4;
#pragma unroll
    for (int ip = 0; ip < 4; ++ip) {
        float lo[4], hi[4];
#pragma unroll
        for (int j = 0; j < 4; ++j) unpk2(lo[j], hi[j], acc[ip][j]);
        int n0 = m0 + ty * 8 + ip * 2;
        if (n0 < NN) {
            float* o = out + (size_t)n0 * ostride + cadd;
#pragma unroll
            for (int j = 0; j < 4; ++j) o[(col0 + j) * cmul] = lo[j];
        }
        if (n0 + 1 < NN) {
            float* o = out + (size_t)(n0 + 1) * ostride + cadd;
#pragma unroll
            for (int j = 0; j < 4; ++j) o[(col0 + j) * cmul] = hi[j];
        }
    }
}

// ---------------- counting sort ----------------
__global__ void k_hist(const int* __restrict__ dst) {
    int i = blockIdx.x * blockDim.x + threadIdx.x;
    if (i * 4 < EE) {
        int4 d4 = ((const int4*)dst)[i];
        atomicAdd(&g_deg[d4.x], 1);
        atomicAdd(&g_deg[d4.y], 1);
        atomicAdd(&g_deg[d4.z], 1);
        atomicAdd(&g_deg[d4.w], 1);
    }
}

// single-pass scan with sentinel lookback (validated R6: 5.2us, correct).
// self-zeroes g_deg for next replay; g_bsum reset by k_scatter.
__global__ __launch_bounds__(256) void k_scan() {
    int t = threadIdx.x, lane = t & 31, wid = t >> 5, bid = blockIdx.x;
    int i = bid * 256 + t;
    int v = (i < NN) ? g_deg[i] : 0;
    int inc = v;
#pragma unroll
    for (int o = 1; o < 32; o <<= 1) {
        int u = __shfl_up_sync(0xffffffffu, inc, o);
        if (lane >= o) inc += u;
    }
    __shared__ int ws[8], ws2[8], s_base;
    if (lane == 31) ws[wid] = inc;
    __syncthreads();
    if (t == 0) {
        int btot = 0;
#pragma unroll
        for (int w = 0; w < 8; ++w) btot += ws[w];
        atomicExch(&g_bsum[bid], -(btot + 1));
    }
    int part = 0;
    if (t < bid) {
        volatile int* vb = g_bsum;
        int sv;
        do { sv = vb[t]; } while (sv >= 0);
        part = -sv - 1;
    }
#pragma unroll
    for (int o = 16; o; o >>= 1) part += __shfl_xor_sync(0xffffffffu, part, o);
    if (lane == 0) ws2[wid] = part;
    __syncthreads();
    if (t == 0) {
        int b = 0;
#pragma unroll
        for (int w = 0; w < 8; ++w) b += ws2[w];
        s_base = b;
    }
    __syncthreads();
    int wpre = 0;
#pragma unroll
    for (int w = 0; w < 8; ++w) wpre += (w < wid) ? ws[w] : 0;
    int excl = s_base + wpre + inc - v;
    if (i < NN) { g_off[i] = excl; g_cur[i] = excl; g_deg[i] = 0; }
    if (bid == NBLK - 1 && t == 255) g_off[NN] = EE;
}

// ---------------- scatter (packed only, x4) + g_bsum reset ----------------
__global__ void k_scatter(const int* __restrict__ src,
                          const int* __restrict__ dst,
                          const int* __restrict__ rel) {
    int j = blockIdx.x * blockDim.x + threadIdx.x;
    if (j < EE / 4) {
        int4 s4 = ((const int4*)src)[j];
        int4 d4 = ((const int4*)dst)[j];
        int4 r4 = ((const int4*)rel)[j];
        int p;
        p = atomicAdd(&g_cur[d4.x], 1); g_packed[p] = s4.x | (r4.x << 16);
        p = atomicAdd(&g_cur[d4.y], 1); g_packed[p] = s4.y | (r4.y << 16);
        p = atomicAdd(&g_cur[d4.z], 1); g_packed[p] = s4.z | (r4.z << 16);
        p = atomicAdd(&g_cur[d4.w], 1); g_packed[p] = s4.w | (r4.w << 16);
    }
    if (blockIdx.x == 0 && threadIdx.x < NBLK) g_bsum[threadIdx.x] = 0;
}

// ---------------- per-node: logits + softmax + head-folded beta ----------
// warp per node. Lane layout: eslot = lane>>2, h = lane&3 (8 edges in flight).
// Pass 1: compute leaky logits (q gather + k via indexed shuffle), write, max.
// Pass 2: wexp in place + denominator. Pass 3: beta (4 lanes/edge, b=lane&3).
__global__ __launch_bounds__(256) void k_mxden(const float* __restrict__ coeff) {
    __shared__ __align__(16) float cf[CC * BB];   // cf[(r*4+h)*4 + b]
    int tid = threadIdx.x;
    if (tid < CC * BB) cf[tid] = coeff[tid];
    __syncthreads();

    int lane = tid & 31, w = tid >> 5;
    int n = blockIdx.x * 8 + w;
    if (n >= NN) return;
    int beg = g_off[n], end = g_off[n + 1];
    if (beg == end) return;

    // preload k row for this node: lane holds k[c = lane]
    float kv = g_qk[n * 64 + 32 + lane];
    int h = lane & 3;
    float* lg = (float*)g_alpha;

    // ---- pass 1: logits + per-head max ----
    float mx = __int_as_float(0xff800000);
    for (int e0 = beg; e0 < end; e0 += 8) {
        int e = e0 + (lane >> 2);
        bool valid = (e < end);
        int pk = g_packed[valid ? e : beg];
        int s = pk & 0xFFFF, r = pk >> 16;
        float q = valid ? g_qk[s * 64 + r * 4 + h] : 0.f;
        float kk = __shfl_sync(0xffffffffu, kv, r * 4 + h);  // uniform exec
        float l = q + kk;
        l = l > 0.f ? l : 0.01f * l;
        if (valid) {
            lg[e0 * 4 + lane] = l;   // == lg[e*4 + h], coalesced
            mx = fmaxf(mx, l);
        }
    }
    mx = fmaxf(mx, __shfl_xor_sync(0xffffffffu, mx, 4));
    mx = fmaxf(mx, __shfl_xor_sync(0xffffffffu, mx, 8));
    mx = fmaxf(mx, __shfl_xor_sync(0xffffffffu, mx, 16));

    // ---- pass 2: wexp in place + denominator ----
    float dsum = 0.f;
    for (int e0 = beg; e0 < end; e0 += 8) {
        int idx = e0 * 4 + lane;
        if (idx < end * 4) {
            float wv = __expf(lg[idx] - mx);
            lg[idx] = wv;
            dsum += wv;
        }
    }
    dsum += __shfl_xor_sync(0xffffffffu, dsum, 4);
    dsum += __shfl_xor_sync(0xffffffffu, dsum, 8);
    dsum += __shfl_xor_sync(0xffffffffu, dsum, 16);
    float inv_self = 1.f / fmaxf(dsum, 1e-16f);
    float inv0 = __shfl_sync(0xffffffffu, inv_self, 0);
    float inv1 = __shfl_sync(0xffffffffu, inv_self, 1);
    float inv2 = __shfl_sync(0xffffffffu, inv_self, 2);
    float inv3 = __shfl_sync(0xffffffffu, inv_self, 3);

    // ---- pass 3: beta (b = lane&3), coalesced write ----
    float* bt = (float*)g_beta;
    for (int e0 = beg; e0 < end; e0 += 8) {
        int idx = e0 * 4 + lane;
        if (idx < end * 4) {
            int e = idx >> 2, b = idx & 3;
            int r = g_packed[e] >> 16;
            float w0 = lg[e * 4 + 0];
            float w1 = lg[e * 4 + 1];
            float w2 = lg[e * 4 + 2];
            float w3 = lg[e * 4 + 3];
            const float* cr = cf + r * 16;
            float bv = inv0 * w0 * cr[b]
                     + inv1 * w1 * cr[4 + b]
                     + inv2 * w2 * cr[8 + b]
                     + inv3 * w3 * cr[12 + b];
            bt[idx] = bv;
        }
    }
}

// ---------------- aggregation: head-free, 4 accumulators, 2 warps/node ------
__global__ __launch_bounds__(256) void k_agg(float* __restrict__ out) {
    __shared__ float s_part[4][64];               // warp B partial output
    int tid = threadIdx.x;
    int lane = tid & 31, w = tid >> 5;
    int node = w >> 1;           // 0..3 within block
    int sub = w & 1;             // 0 = warp A, 1 = warp B
    int n = blockIdx.x * 4 + node;
    bool active = (n < NN);

    int beg = 0, end = 0;
    if (active) { beg = g_off[n]; end = g_off[n + 1]; }
    int len = end - beg;
    int half = (len + 1) >> 1;
    int mybeg = beg + (sub ? half : 0);
    int myend = sub ? end : (beg + half);

    ull acc00 = 0ull, acc01 = 0ull, acc10 = 0ull, acc11 = 0ull;

    if (mybeg < myend) {
        int pk = g_packed[mybeg];
        for (int e = mybeg; e < myend; ++e) {
            int pkc = pk;
            if (e + 1 < myend) pk = g_packed[e + 1];

            int s = pkc & 0xFFFF;
            float4 bt = g_beta[e];       // uniform per warp
            const float4* yr = (const float4*)(g_y + (size_t)s * 256);
            float4 y0 = yr[lane];        // u = lane,    b0..b3
            float4 y1 = yr[32 + lane];   // u = lane+32, b0..b3
            ull b01 = pack2(bt.x, bt.y);
            ull b23 = pack2(bt.z, bt.w);
            fma2(acc00, b01, pack2(y0.x, y0.y));
            fma2(acc01, b23, pack2(y0.z, y0.w));
            fma2(acc10, b01, pack2(y1.x, y1.y));
            fma2(acc11, b23, pack2(y1.z, y1.w));
        }
    }

    float o0 = 0.f, o1 = 0.f;
    {
        float l0, h0, l1, h1, l2, h2, l3, h3;
        unpk2(l0, h0, acc00);
        unpk2(l1, h1, acc01);
        unpk2(l2, h2, acc10);
        unpk2(l3, h3, acc11);
        o0 = (l0 + h0) + (l1 + h1);
        o1 = (l2 + h2) + (l3 + h3);
    }

    if (sub == 1) {
        s_part[node][lane] = o0;
        s_part[node][32 + lane] = o1;
    }
    __syncthreads();

    if (sub == 0 && active) {
        o0 += s_part[node][lane];
        o1 += s_part[node][32 + lane];
        out[n * UU + lane] = 0.25f * o0;
        out[n * UU + 32 + lane] = 0.25f * o1;
    }
}

// ---------------- launch ----------------
extern "C" void kernel_launch(void* const* d_in, const int* in_sizes, int n_in,
                              void* d_out, int out_size) {
    const float* x     = (const float*)d_in[0];
    const float* basis = (const float*)d_in[1];
    const float* coeff = (const float*)d_in[2];
    const float* aq    = (const float*)d_in[3];
    const float* ak    = (const float*)d_in[4];
    const int*   src   = (const int*)d_in[5];
    const int*   dst   = (const int*)d_in[6];
    const int*   rel   = (const int*)d_in[7];
    float* out = (float*)d_out;

    float* d_y;   cudaGetSymbolAddress((void**)&d_y, g_y);
    float* d_qk;  cudaGetSymbolAddress((void**)&d_qk, g_qk);
    float* d_wqk; cudaGetSymbolAddress((void**)&d_wqk, g_wqk);

    cudaFuncSetAttribute(k_gemm, cudaFuncAttributeMaxDynamicSharedMemorySize, GEMM_SMEM);

    cudaStream_t s1 = 0, s2 = 0;
    bool fork = s_forkOK;
    if (fork) {
        s1 = s_s1; s2 = s_s2;
        cudaEventRecord(s_evRoot, 0);
        cudaStreamWaitEvent(s1, s_evRoot, 0);
        cudaStreamWaitEvent(s2, s_evRoot, 0);
    }

    // --- side stream 1: prep -> qk GEMM ---
    k_prep<<<32, 256, 0, s1>>>(coeff, basis, aq, ak);
    k_gemm<<<dim3((NN + GROWS - 1) / GROWS, 1), 256, GEMM_SMEM, s1>>>(
        x, d_wqk, d_qk, 64, 1, 0, 0, 0);

    // --- side stream 2: y GEMM ---
    k_gemm<<<dim3((NN + GROWS - 1) / GROWS, BB), 256, GEMM_SMEM, s2>>>(
        x, basis, d_y, 256, 4, 0, FF * UU, 1);

    if (fork) {
        cudaEventRecord(s_evA, s1);
        cudaEventRecord(s_evB, s2);
    }

    // --- main stream: counting sort (no qk dependency anywhere) ---
    k_hist<<<(EE / 4 + 255) / 256, 256>>>(dst);
    k_scan<<<NBLK, 256>>>();
    k_scatter<<<(EE / 4 + 255) / 256, 256>>>(src, dst, rel);

    // mxden reads g_qk -> wait for qk GEMM
    if (fork) cudaStreamWaitEvent(0, s_evA, 0);
    k_mxden<<<(NN + 7) / 8, 256>>>(coeff);

    if (fork) cudaStreamWaitEvent(0, s_evB, 0);
    k_agg<<<(NN + 3) / 4, 256>>>(out);
}

// round 13
// speedup vs baseline: 3.5272x; 1.0002x over previous
#include <cuda_runtime.h>

#define NN 20000
#define FF 256
#define RR 8
#define HH 4
#define UU 64
#define BB 4
#define CC 32   // R*H
#define EE 320000
#define NBLK 79  // ceil(NN/256)

typedef unsigned long long ull;

// ---------------- f32x2 packed math helpers ----------------
__device__ __forceinline__ ull splat2(float v) {
    ull r; asm("mov.b64 %0, {%1, %1};" : "=l"(r) : "f"(v)); return r;
}
__device__ __forceinline__ ull pack2(float lo, float hi) {
    ull r; asm("mov.b64 %0, {%1, %2};" : "=l"(r) : "f"(lo), "f"(hi)); return r;
}
__device__ __forceinline__ void fma2(ull& d, ull a, ull b) {
    asm("fma.rn.f32x2 %0, %1, %2, %0;" : "+l"(d) : "l"(a), "l"(b));
}
__device__ __forceinline__ ull mul2(ull a, ull b) {
    ull d; asm("mul.rn.f32x2 %0, %1, %2;" : "=l"(d) : "l"(a), "l"(b)); return d;
}
__device__ __forceinline__ void unpk2(float& lo, float& hi, ull v) {
    asm("mov.b64 {%0, %1}, %2;" : "=f"(lo), "=f"(hi) : "l"(v));
}

// ---------------- device scratch ----------------
__device__ float  g_y[NN * BB * UU];   // y[n][u*4 + b]  (interleaved, 20.48 MB)
__device__ float  g_qk[NN * 64];       // [n][c] c<32: q(c=r*4+h), c>=32: k
__device__ float  g_wqk[FF * 64];      // [f][c] k-major weight for qk GEMM
__device__ int    g_deg[NN];           // zero at init; re-zeroed by k_scan
__device__ int    g_off[NN + 1];
__device__ int    g_cur[NN];
__device__ int    g_bsum[NBLK];        // 0 = not ready; -(sum+1) = ready. reset by k_scatter
__device__ int    g_packed[EE];        // src | (rel<<16), CSR-sorted by dst
__device__ float4 g_alpha[EE];         // per-CSR-slot: logit -> wexp per head
__device__ float4 g_beta[EE];          // per-CSR-slot: head-folded weights per b

// ---------------- static stream/event bootstrap ----------------
static cudaStream_t s_s1 = 0, s_s2 = 0;
static cudaEvent_t  s_evRoot = 0, s_evA = 0, s_evB = 0;
static bool s_forkOK = false;
namespace {
struct Boot {
    Boot() {
        bool ok = true;
        ok &= (cudaStreamCreateWithFlags(&s_s1, cudaStreamNonBlocking) == cudaSuccess);
        ok &= (cudaStreamCreateWithFlags(&s_s2, cudaStreamNonBlocking) == cudaSuccess);
        ok &= (cudaEventCreateWithFlags(&s_evRoot, cudaEventDisableTiming) == cudaSuccess);
        ok &= (cudaEventCreateWithFlags(&s_evA, cudaEventDisableTiming) == cudaSuccess);
        ok &= (cudaEventCreateWithFlags(&s_evB, cudaEventDisableTiming) == cudaSuccess);
        s_forkOK = ok;
    }
} s_boot;
}

// ---------------- K0: qk weight build (smem-staged, coalesced) ----------------
__global__ __launch_bounds__(256) void k_prep(const float* __restrict__ coeff,
                                              const float* __restrict__ basis,
                                              const float* __restrict__ aq,
                                              const float* __restrict__ ak) {
    __shared__ float bs[BB][8][UU + 1];
    __shared__ float aqs[CC][UU + 1];
    __shared__ float aks[CC][UU + 1];
    int t = threadIdx.x;
    int f_base = blockIdx.x * 8;

    for (int i = t; i < CC * UU; i += 256) {
        int c = i >> 6, u = i & 63;
        aqs[c][u] = aq[i];
        aks[c][u] = ak[i];
    }
    for (int i = t; i < BB * 8 * UU; i += 256) {
        int b = i >> 9;
        int rem = i & 511;
        int fl = rem >> 6, u = rem & 63;
        bs[b][fl][u] = basis[(b * FF + f_base + fl) * UU + u];
    }
    __syncthreads();

    int c = t >> 3, fl = t & 7;
    float sq = 0.f, sk = 0.f;
#pragma unroll
    for (int b = 0; b < BB; ++b) {
        float dq = 0.f, dk = 0.f;
        const float* bp = bs[b][fl];
        const float* aqc = aqs[c];
        const float* akc = aks[c];
#pragma unroll 8
        for (int u = 0; u < UU; ++u) {
            float bv = bp[u];
            dq += bv * aqc[u];
            dk += bv * akc[u];
        }
        float cb = coeff[c * BB + b];
        sq += cb * dq;
        sk += cb * dk;
    }
    int f = f_base + fl;
    g_wqk[f * 64 + c]      = sq;
    g_wqk[f * 64 + 32 + c] = sk;
}

// ---------------- K1: generic 128x64 FFMA2 GEMM ----------------
#define GROWS 128
#define KC 128
#define XPAD 132
#define GEMM_SMEM ((KC * XPAD + KC * 64) * 4)

__global__ __launch_bounds__(256, 2) void k_gemm(const float* __restrict__ x,
                                                 const float* __restrict__ w,
                                                 float* __restrict__ out,
                                                 int ostride, int cmul, int cadd0,
                                                 int bstride, int caddstep) {
    extern __shared__ float sm[];
    float* xs = sm;                 // [KC][XPAD] transposed x chunk
    float* ws = sm + KC * XPAD;     // [KC][64]
    int tid = threadIdx.x;
    int tx = tid & 15, ty = tid >> 4;
    int m0 = blockIdx.x * GROWS;
    const float* wb = w + (size_t)blockIdx.y * bstride;
    int cadd = cadd0 + blockIdx.y * caddstep;

    ull acc[4][4];
#pragma unroll
    for (int i = 0; i < 4; ++i)
#pragma unroll
        for (int j = 0; j < 4; ++j) acc[i][j] = 0ull;

    for (int kc = 0; kc < 2; ++kc) {
        if (kc) __syncthreads();
        const float4* w4 = (const float4*)(wb + kc * KC * 64);
        float4* ws4 = (float4*)ws;
        for (int i = tid; i < KC * 16; i += 256) ws4[i] = w4[i];
        const float4* x4 = (const float4*)x;
        for (int i = tid; i < GROWS * 32; i += 256) {
            int row = i >> 5, k4 = i & 31;
            int n = m0 + row;
            float4 v = make_float4(0.f, 0.f, 0.f, 0.f);
            if (n < NN) v = x4[n * 64 + kc * 32 + k4];
            xs[(k4 * 4 + 0) * XPAD + row] = v.x;
            xs[(k4 * 4 + 1) * XPAD + row] = v.y;
            xs[(k4 * 4 + 2) * XPAD + row] = v.z;
            xs[(k4 * 4 + 3) * XPAD + row] = v.w;
        }
        __syncthreads();

        const float* wp = ws + tx * 4;
        const float* xp = xs + ty * 8;
#pragma unroll 8
        for (int k = 0; k < KC; ++k) {
            float4 bv = *(const float4*)(wp + k * 64);
            const float* xr = xp + k * XPAD;
            ull a0 = *(const ull*)(xr);
            ull a1 = *(const ull*)(xr + 2);
            ull a2 = *(const ull*)(xr + 4);
            ull a3 = *(const ull*)(xr + 6);
            ull s0 = splat2(bv.x), s1 = splat2(bv.y),
                s2 = splat2(bv.z), s3 = splat2(bv.w);
            fma2(acc[0][0], a0, s0); fma2(acc[1][0], a1, s0);
            fma2(acc[2][0], a2, s0); fma2(acc[3][0], a3, s0);
            fma2(acc[0][1], a0, s1); fma2(acc[1][1], a1, s1);
            fma2(acc[2][1], a2, s1); fma2(acc[3][1], a3, s1);
            fma2(acc[0][2], a0, s2); fma2(acc[1][2], a1, s2);
            fma2(acc[2][2], a2, s2); fma2(acc[3][2], a3, s2);
            fma2(acc[0][3], a0, s3); fma2(acc[1][3], a1, s3);
            fma2(acc[2][3], a2, s3); fma2(acc[3][3], a3, s3);
        }
    }

    int col0 = tx * 4;
#pragma unroll
    for (int ip = 0; ip < 4; ++ip) {
        float lo[4], hi[4];
#pragma unroll
        for (int j = 0; j < 4; ++j) unpk2(lo[j], hi[j], acc[ip][j]);
        int n0 = m0 + ty * 8 + ip * 2;
        if (n0 < NN) {
            float* o = out + (size_t)n0 * ostride + cadd;
#pragma unroll
            for (int j = 0; j < 4; ++j) o[(col0 + j) * cmul] = lo[j];
        }
        if (n0 + 1 < NN) {
            float* o = out + (size_t)(n0 + 1) * ostride + cadd;
#pragma unroll
            for (int j = 0; j < 4; ++j) o[(col0 + j) * cmul] = hi[j];
        }
    }
}

// ---------------- counting sort ----------------
__global__ void k_hist(const int* __restrict__ dst) {
    int i = blockIdx.x * blockDim.x + threadIdx.x;
    if (i * 4 < EE) {
        int4 d4 = ((const int4*)dst)[i];
        atomicAdd(&g_deg[d4.x], 1);
        atomicAdd(&g_deg[d4.y], 1);
        atomicAdd(&g_deg[d4.z], 1);
        atomicAdd(&g_deg[d4.w], 1);
    }
}

// single-pass scan with sentinel lookback; self-zeroes g_deg.
__global__ __launch_bounds__(256) void k_scan() {
    int t = threadIdx.x, lane = t & 31, wid = t >> 5, bid = blockIdx.x;
    int i = bid * 256 + t;
    int v = (i < NN) ? g_deg[i] : 0;
    int inc = v;
#pragma unroll
    for (int o = 1; o < 32; o <<= 1) {
        int u = __shfl_up_sync(0xffffffffu, inc, o);
        if (lane >= o) inc += u;
    }
    __shared__ int ws[8], ws2[8], s_base;
    if (lane == 31) ws[wid] = inc;
    __syncthreads();
    if (t == 0) {
        int btot = 0;
#pragma unroll
        for (int w = 0; w < 8; ++w) btot += ws[w];
        atomicExch(&g_bsum[bid], -(btot + 1));
    }
    int part = 0;
    if (t < bid) {
        volatile int* vb = g_bsum;
        int sv;
        do { sv = vb[t]; } while (sv >= 0);
        part = -sv - 1;
    }
#pragma unroll
    for (int o = 16; o; o >>= 1) part += __shfl_xor_sync(0xffffffffu, part, o);
    if (lane == 0) ws2[wid] = part;
    __syncthreads();
    if (t == 0) {
        int b = 0;
#pragma unroll
        for (int w = 0; w < 8; ++w) b += ws2[w];
        s_base = b;
    }
    __syncthreads();
    int wpre = 0;
#pragma unroll
    for (int w = 0; w < 8; ++w) wpre += (w < wid) ? ws[w] : 0;
    int excl = s_base + wpre + inc - v;
    if (i < NN) { g_off[i] = excl; g_cur[i] = excl; g_deg[i] = 0; }
    if (bid == NBLK - 1 && t == 255) g_off[NN] = EE;
}

// ---------------- scatter (packed only, x4) + g_bsum reset ----------------
__global__ void k_scatter(const int* __restrict__ src,
                          const int* __restrict__ dst,
                          const int* __restrict__ rel) {
    int j = blockIdx.x * blockDim.x + threadIdx.x;
    if (j < EE / 4) {
        int4 s4 = ((const int4*)src)[j];
        int4 d4 = ((const int4*)dst)[j];
        int4 r4 = ((const int4*)rel)[j];
        int p;
        p = atomicAdd(&g_cur[d4.x], 1); g_packed[p] = s4.x | (r4.x << 16);
        p = atomicAdd(&g_cur[d4.y], 1); g_packed[p] = s4.y | (r4.y << 16);
        p = atomicAdd(&g_cur[d4.z], 1); g_packed[p] = s4.z | (r4.z << 16);
        p = atomicAdd(&g_cur[d4.w], 1); g_packed[p] = s4.w | (r4.w << 16);
    }
    if (blockIdx.x == 0 && threadIdx.x < NBLK) g_bsum[threadIdx.x] = 0;
}

// ---------------- per-node: logits + softmax + head-folded beta ----------
__global__ __launch_bounds__(256) void k_mxden(const float* __restrict__ coeff) {
    __shared__ __align__(16) float cf[CC * BB];   // cf[(r*4+h)*4 + b]
    int tid = threadIdx.x;
    if (tid < CC * BB) cf[tid] = coeff[tid];
    __syncthreads();

    int lane = tid & 31, w = tid >> 5;
    int n = blockIdx.x * 8 + w;
    if (n >= NN) return;
    int beg = g_off[n], end = g_off[n + 1];
    if (beg == end) return;

    // preload k row for this node: lane holds k[c = lane]
    float kv = g_qk[n * 64 + 32 + lane];
    int h = lane & 3;
    float* lg = (float*)g_alpha;

    // ---- pass 1: logits + per-head max ----
    float mx = __int_as_float(0xff800000);
    for (int e0 = beg; e0 < end; e0 += 8) {
        int e = e0 + (lane >> 2);
        bool valid = (e < end);
        int pk = g_packed[valid ? e : beg];
        int s = pk & 0xFFFF, r = pk >> 16;
        float q = valid ? g_qk[s * 64 + r * 4 + h] : 0.f;
        float kk = __shfl_sync(0xffffffffu, kv, r * 4 + h);  // uniform exec
        float l = q + kk;
        l = l > 0.f ? l : 0.01f * l;
        if (valid) {
            lg[e0 * 4 + lane] = l;   // == lg[e*4 + h], coalesced
            mx = fmaxf(mx, l);
        }
    }
    mx = fmaxf(mx, __shfl_xor_sync(0xffffffffu, mx, 4));
    mx = fmaxf(mx, __shfl_xor_sync(0xffffffffu, mx, 8));
    mx = fmaxf(mx, __shfl_xor_sync(0xffffffffu, mx, 16));

    // ---- pass 2: wexp in place + denominator ----
    float dsum = 0.f;
    for (int e0 = beg; e0 < end; e0 += 8) {
        int idx = e0 * 4 + lane;
        if (idx < end * 4) {
            float wv = __expf(lg[idx] - mx);
            lg[idx] = wv;
            dsum += wv;
        }
    }
    dsum += __shfl_xor_sync(0xffffffffu, dsum, 4);
    dsum += __shfl_xor_sync(0xffffffffu, dsum, 8);
    dsum += __shfl_xor_sync(0xffffffffu, dsum, 16);
    float inv_self = 1.f / fmaxf(dsum, 1e-16f);
    float inv0 = __shfl_sync(0xffffffffu, inv_self, 0);
    float inv1 = __shfl_sync(0xffffffffu, inv_self, 1);
    float inv2 = __shfl_sync(0xffffffffu, inv_self, 2);
    float inv3 = __shfl_sync(0xffffffffu, inv_self, 3);

    // ---- pass 3: beta (b = lane&3), coalesced write ----
    float* bt = (float*)g_beta;
    for (int e0 = beg; e0 < end; e0 += 8) {
        int idx = e0 * 4 + lane;
        if (idx < end * 4) {
            int e = idx >> 2, b = idx & 3;
            int r = g_packed[e] >> 16;
            float w0 = lg[e * 4 + 0];
            float w1 = lg[e * 4 + 1];
            float w2 = lg[e * 4 + 2];
            float w3 = lg[e * 4 + 3];
            const float* cr = cf + r * 16;
            float bv = inv0 * w0 * cr[b]
                     + inv1 * w1 * cr[4 + b]
                     + inv2 * w2 * cr[8 + b]
                     + inv3 * w3 * cr[12 + b];
            bt[idx] = bv;
        }
    }
}

// ---------------- aggregation: head-free, 4 accs, 2 warps/node,
//                   software-pipelined gather (safe now: low reg pressure) ----
__global__ __launch_bounds__(256) void k_agg(float* __restrict__ out) {
    __shared__ float s_part[4][64];               // warp B partial output
    int tid = threadIdx.x;
    int lane = tid & 31, w = tid >> 5;
    int node = w >> 1;           // 0..3 within block
    int sub = w & 1;             // 0 = warp A, 1 = warp B
    int n = blockIdx.x * 4 + node;
    bool active = (n < NN);

    int beg = 0, end = 0;
    if (active) { beg = g_off[n]; end = g_off[n + 1]; }
    int len = end - beg;
    int half = (len + 1) >> 1;
    int mybeg = beg + (sub ? half : 0);
    int myend = sub ? end : (beg + half);

    ull acc00 = 0ull, acc01 = 0ull, acc10 = 0ull, acc11 = 0ull;

    if (mybeg < myend) {
        // ---- prologue: fully load edge mybeg ----
        int sA = g_packed[mybeg] & 0xFFFF;
        float4 btA = g_beta[mybeg];
        const float4* yrA = (const float4*)(g_y + (size_t)sA * 256);
        float4 y0A = yrA[lane];
        float4 y1A = yrA[32 + lane];

        for (int e = mybeg; e < myend; ++e) {
            // ---- prefetch edge e+1 (loads overlap edge-e FMA chain) ----
            float4 btB = btA, y0B = y0A, y1B = y1A;
            if (e + 1 < myend) {
                int sB = g_packed[e + 1] & 0xFFFF;
                btB = g_beta[e + 1];
                const float4* yrB = (const float4*)(g_y + (size_t)sB * 256);
                y0B = yrB[lane];
                y1B = yrB[32 + lane];
            }

            // ---- accumulate edge e ----
            ull b01 = pack2(btA.x, btA.y);
            ull b23 = pack2(btA.z, btA.w);
            fma2(acc00, b01, pack2(y0A.x, y0A.y));
            fma2(acc01, b23, pack2(y0A.z, y0A.w));
            fma2(acc10, b01, pack2(y1A.x, y1A.y));
            fma2(acc11, b23, pack2(y1A.z, y1A.w));

            // ---- rotate ----
            btA = btB; y0A = y0B; y1A = y1B;
        }
    }

    float o0, o1;
    {
        float l0, h0, l1, h1, l2, h2, l3, h3;
        unpk2(l0, h0, acc00);
        unpk2(l1, h1, acc01);
        unpk2(l2, h2, acc10);
        unpk2(l3, h3, acc11);
        o0 = (l0 + h0) + (l1 + h1);
        o1 = (l2 + h2) + (l3 + h3);
    }

    if (sub == 1) {
        s_part[node][lane] = o0;
        s_part[node][32 + lane] = o1;
    }
    __syncthreads();

    if (sub == 0 && active) {
        o0 += s_part[node][lane];
        o1 += s_part[node][32 + lane];
        out[n * UU + lane] = 0.25f * o0;
        out[n * UU + 32 + lane] = 0.25f * o1;
    }
}

// ---------------- launch ----------------
extern "C" void kernel_launch(void* const* d_in, const int* in_sizes, int n_in,
                              void* d_out, int out_size) {
    const float* x     = (const float*)d_in[0];
    const float* basis = (const float*)d_in[1];
    const float* coeff = (const float*)d_in[2];
    const float* aq    = (const float*)d_in[3];
    const float* ak    = (const float*)d_in[4];
    const int*   src   = (const int*)d_in[5];
    const int*   dst   = (const int*)d_in[6];
    const int*   rel   = (const int*)d_in[7];
    float* out = (float*)d_out;

    float* d_y;   cudaGetSymbolAddress((void**)&d_y, g_y);
    float* d_qk;  cudaGetSymbolAddress((void**)&d_qk, g_qk);
    float* d_wqk; cudaGetSymbolAddress((void**)&d_wqk, g_wqk);

    cudaFuncSetAttribute(k_gemm, cudaFuncAttributeMaxDynamicSharedMemorySize, GEMM_SMEM);

    cudaStream_t s1 = 0, s2 = 0;
    bool fork = s_forkOK;
    if (fork) {
        s1 = s_s1; s2 = s_s2;
        cudaEventRecord(s_evRoot, 0);
        cudaStreamWaitEvent(s1, s_evRoot, 0);
        cudaStreamWaitEvent(s2, s_evRoot, 0);
    }

    // --- side stream 1: prep -> qk GEMM ---
    k_prep<<<32, 256, 0, s1>>>(coeff, basis, aq, ak);
    k_gemm<<<dim3((NN + GROWS - 1) / GROWS, 1), 256, GEMM_SMEM, s1>>>(
        x, d_wqk, d_qk, 64, 1, 0, 0, 0);

    // --- side stream 2: y GEMM ---
    k_gemm<<<dim3((NN + GROWS - 1) / GROWS, BB), 256, GEMM_SMEM, s2>>>(
        x, basis, d_y, 256, 4, 0, FF * UU, 1);

    if (fork) {
        cudaEventRecord(s_evA, s1);
        cudaEventRecord(s_evB, s2);
    }

    // --- main stream: counting sort (no qk dependency anywhere) ---
    k_hist<<<(EE / 4 + 255) / 256, 256>>>(dst);
    k_scan<<<NBLK, 256>>>();
    k_scatter<<<(EE / 4 + 255) / 256, 256>>>(src, dst, rel);

    // mxden reads g_qk -> wait for qk GEMM
    if (fork) cudaStreamWaitEvent(0, s_evA, 0);
    k_mxden<<<(NN + 7) / 8, 256>>>(coeff);

    if (fork) cudaStreamWaitEvent(0, s_evB, 0);
    k_agg<<<(NN + 3) / 4, 256>>>(out);
}

// round 15
// speedup vs baseline: 3.8341x; 1.0870x over previous
#include <cuda_runtime.h>
#include <cstdint>

#define NN 20000
#define FF 256
#define RR 8
#define HH 4
#define UU 64
#define BB 4
#define CC 32   // R*H
#define EE 320000
#define NBLK 79  // ceil(NN/256)

typedef unsigned long long ull;

// ---------------- f32x2 packed math helpers ----------------
__device__ __forceinline__ ull splat2(float v) {
    ull r; asm("mov.b64 %0, {%1, %1};" : "=l"(r) : "f"(v)); return r;
}
__device__ __forceinline__ ull pack2(float lo, float hi) {
    ull r; asm("mov.b64 %0, {%1, %2};" : "=l"(r) : "f"(lo), "f"(hi)); return r;
}
__device__ __forceinline__ void fma2(ull& d, ull a, ull b) {
    asm("fma.rn.f32x2 %0, %1, %2, %0;" : "+l"(d) : "l"(a), "l"(b));
}
__device__ __forceinline__ ull mul2(ull a, ull b) {
    ull d; asm("mul.rn.f32x2 %0, %1, %2;" : "=l"(d) : "l"(a), "l"(b)); return d;
}
__device__ __forceinline__ void unpk2(float& lo, float& hi, ull v) {
    asm("mov.b64 {%0, %1}, %2;" : "=f"(lo), "=f"(hi) : "l"(v));
}

// ---------------- tf32 split + mma.sync helpers ----------------
__device__ __forceinline__ float2 split_tf32(float v) {
    uint32_t hi; asm("cvt.rna.tf32.f32 %0, %1;" : "=r"(hi) : "f"(v));
    float hif = __uint_as_float(hi);
    uint32_t lo; asm("cvt.rna.tf32.f32 %0, %1;" : "=r"(lo) : "f"(v - hif));
    return make_float2(hif, __uint_as_float(lo));
}
__device__ __forceinline__ void mma_tf32(float& d0, float& d1, float& d2, float& d3,
                                         uint32_t a0, uint32_t a1, uint32_t a2, uint32_t a3,
                                         uint32_t b0, uint32_t b1) {
    asm volatile(
        "mma.sync.aligned.m16n8k8.row.col.f32.tf32.tf32.f32 "
        "{%0,%1,%2,%3}, {%4,%5,%6,%7}, {%8,%9}, {%0,%1,%2,%3};"
        : "+f"(d0), "+f"(d1), "+f"(d2), "+f"(d3)
        : "r"(a0), "r"(a1), "r"(a2), "r"(a3), "r"(b0), "r"(b1));
}

// ---------------- device scratch ----------------
__device__ float  g_y[NN * BB * UU];   // y[n][u*4 + b]  (interleaved, 20.48 MB)
__device__ float  g_qk[NN * 64];       // [n][c] c<32: q(c=r*4+h), c>=32: k
__device__ float  g_wqk[FF * 64];      // [f][c] k-major weight for qk GEMM
__device__ float2 g_wt2[BB * FF * UU]; // W^T tf32 (hi,lo): [b][f][u]  (512 KB)
__device__ int    g_deg[NN];
__device__ int    g_off[NN + 1];
__device__ int    g_cur[NN];
__device__ int    g_bsum[NBLK];
__device__ int    g_packed[EE];
__device__ float4 g_alpha[EE];
__device__ float4 g_beta[EE];

// ---------------- static stream/event bootstrap ----------------
static cudaStream_t s_s1 = 0, s_s2 = 0;
static cudaEvent_t  s_evRoot = 0, s_evA = 0, s_evB = 0;
static bool s_forkOK = false;
namespace {
struct Boot {
    Boot() {
        bool ok = true;
        ok &= (cudaStreamCreateWithFlags(&s_s1, cudaStreamNonBlocking) == cudaSuccess);
        ok &= (cudaStreamCreateWithFlags(&s_s2, cudaStreamNonBlocking) == cudaSuccess);
        ok &= (cudaEventCreateWithFlags(&s_evRoot, cudaEventDisableTiming) == cudaSuccess);
        ok &= (cudaEventCreateWithFlags(&s_evA, cudaEventDisableTiming) == cudaSuccess);
        ok &= (cudaEventCreateWithFlags(&s_evB, cudaEventDisableTiming) == cudaSuccess);
        s_forkOK = ok;
    }
} s_boot;
}

// ---------------- K-cvtW: build W^T tf32 (hi,lo)  [b][f][u] ------
__global__ void k_cvtw(const float* __restrict__ basis) {
    int idx = blockIdx.x * blockDim.x + threadIdx.x;
    if (idx >= BB * FF * UU) return;
    int b = idx >> 14;
    int rem = idx & 16383;
    int f = rem >> 6, u = rem & 63;
    g_wt2[idx] = split_tf32(basis[(b * FF + f) * UU + u]);
}

// ---------------- K-yhmma: tf32-split HMMA y-GEMM --------------------------
// Block: 256 thr (8 warps), tile 128 rows x 64 u-cols for b-slice blockIdx.y.
// Warp w: rows (w&3)*32, cols (w>>2)*32 -> 2 m-groups x 4 n-tiles of m16n8k8.
// K = 256 in 8 chunks of 32; x and W staged as (hi,lo) float2 in smem.
#define XS2_STR 37
#define WS2_STR 68
#define YH_XS_BYTES (128 * XS2_STR * 8)           // 37888
#define YH_SMEM (YH_XS_BYTES + 32 * WS2_STR * 8)  // + 17408 = 55296

__global__ __launch_bounds__(256) void k_yhmma(const float* __restrict__ x) {
    extern __shared__ char sm8[];
    float2* xs2 = (float2*)sm8;                    // [128][XS2_STR]
    float2* ws2 = (float2*)(sm8 + YH_XS_BYTES);    // [32][WS2_STR]
    int t = threadIdx.x;
    int lane = t & 31, w = t >> 5;
    int wm = w & 3, wn = w >> 2;
    int m0 = blockIdx.x * 128;
    int bsl = blockIdx.y;
    int lg = lane >> 2, lt = lane & 3;             // groupID, threadID_in_group

    float d[2][4][4];
#pragma unroll
    for (int mg = 0; mg < 2; ++mg)
#pragma unroll
        for (int nt = 0; nt < 4; ++nt)
#pragma unroll
            for (int i = 0; i < 4; ++i) d[mg][nt][i] = 0.f;

    const float4* x4 = (const float4*)x;
    const float2* wsrc = g_wt2 + bsl * (FF * UU);

    for (int kc = 0; kc < 8; ++kc) {
        if (kc) __syncthreads();
        // ---- stage x chunk: 128 rows x 32 k, split to tf32 (hi,lo) ----
        {
            int row = t >> 1;
            int hf = t & 1;
            int n = m0 + row;
#pragma unroll
            for (int i = 0; i < 4; ++i) {
                int c4 = hf * 4 + i;
                float4 v = make_float4(0.f, 0.f, 0.f, 0.f);
                if (n < NN) v = x4[n * 64 + kc * 8 + c4];
                float2* dst = xs2 + row * XS2_STR + c4 * 4;
                dst[0] = split_tf32(v.x);
                dst[1] = split_tf32(v.y);
                dst[2] = split_tf32(v.z);
                dst[3] = split_tf32(v.w);
            }
        }
        // ---- stage W chunk: 32 k x 64 u float2 (already split) ----
        {
#pragma unroll
            for (int i = 0; i < 4; ++i) {
                int gid = t + i * 256;          // uint4 = 2 float2
                int k = gid >> 5;
                int u = (gid & 31) * 2;
                uint4 v = *(const uint4*)(wsrc + (kc * 32 + k) * UU + u);
                *(uint4*)(ws2 + k * WS2_STR + u) = v;
            }
        }
        __syncthreads();

        // ---- 4 k-steps of 8 ----
#pragma unroll
        for (int ks = 0; ks < 4; ++ks) {
            int k0 = ks * 8;
            uint2 aF[2][4];
#pragma unroll
            for (int mg = 0; mg < 2; ++mg) {
                const uint2* xr = (const uint2*)(xs2 + (wm * 32 + mg * 16 + lg) * XS2_STR + k0 + lt);
                const uint2* xr8 = (const uint2*)(xs2 + (wm * 32 + mg * 16 + lg + 8) * XS2_STR + k0 + lt);
                aF[mg][0] = xr[0];
                aF[mg][1] = xr8[0];
                aF[mg][2] = xr[4];
                aF[mg][3] = xr8[4];
            }
            uint2 bF[4][2];
#pragma unroll
            for (int nt = 0; nt < 4; ++nt) {
                const uint2* wr = (const uint2*)(ws2 + (k0 + lt) * WS2_STR + wn * 32 + nt * 8 + lg);
                const uint2* wr4 = (const uint2*)(ws2 + (k0 + lt + 4) * WS2_STR + wn * 32 + nt * 8 + lg);
                bF[nt][0] = wr[0];
                bF[nt][1] = wr4[0];
            }
#pragma unroll
            for (int mg = 0; mg < 2; ++mg)
#pragma unroll
                for (int nt = 0; nt < 4; ++nt) {
                    float* dd = d[mg][nt];
                    // hi * hi
                    mma_tf32(dd[0], dd[1], dd[2], dd[3],
                             aF[mg][0].x, aF[mg][1].x, aF[mg][2].x, aF[mg][3].x,
                             bF[nt][0].x, bF[nt][1].x);
                    // hi * lo
                    mma_tf32(dd[0], dd[1], dd[2], dd[3],
                             aF[mg][0].x, aF[mg][1].x, aF[mg][2].x, aF[mg][3].x,
                             bF[nt][0].y, bF[nt][1].y);
                    // lo * hi
                    mma_tf32(dd[0], dd[1], dd[2], dd[3],
                             aF[mg][0].y, aF[mg][1].y, aF[mg][2].y, aF[mg][3].y,
                             bF[nt][0].x, bF[nt][1].x);
                }
        }
    }

    // ---- epilogue: D -> y[n][u*4 + b] ----
#pragma unroll
    for (int mg = 0; mg < 2; ++mg)
#pragma unroll
        for (int nt = 0; nt < 4; ++nt) {
            int r0 = m0 + wm * 32 + mg * 16 + lg;
            int u0 = wn * 32 + nt * 8 + lt * 2;
            const float* dd = d[mg][nt];
            if (r0 < NN) {
                g_y[(size_t)r0 * 256 + u0 * 4 + bsl] = dd[0];
                g_y[(size_t)r0 * 256 + (u0 + 1) * 4 + bsl] = dd[1];
            }
            if (r0 + 8 < NN) {
                g_y[(size_t)(r0 + 8) * 256 + u0 * 4 + bsl] = dd[2];
                g_y[(size_t)(r0 + 8) * 256 + (u0 + 1) * 4 + bsl] = dd[3];
            }
        }
}

// ---------------- K0: qk weight build (smem-staged, coalesced) ----------------
__global__ __launch_bounds__(256) void k_prep(const float* __restrict__ coeff,
                                              const float* __restrict__ basis,
                                              const float* __restrict__ aq,
                                              const float* __restrict__ ak) {
    __shared__ float bs[BB][8][UU + 1];
    __shared__ float aqs[CC][UU + 1];
    __shared__ float aks[CC][UU + 1];
    int t = threadIdx.x;
    int f_base = blockIdx.x * 8;

    for (int i = t; i < CC * UU; i += 256) {
        int c = i >> 6, u = i & 63;
        aqs[c][u] = aq[i];
        aks[c][u] = ak[i];
    }
    for (int i = t; i < BB * 8 * UU; i += 256) {
        int b = i >> 9;
        int rem = i & 511;
        int fl = rem >> 6, u = rem & 63;
        bs[b][fl][u] = basis[(b * FF + f_base + fl) * UU + u];
    }
    __syncthreads();

    int c = t >> 3, fl = t & 7;
    float sq = 0.f, sk = 0.f;
#pragma unroll
    for (int b = 0; b < BB; ++b) {
        float dq = 0.f, dk = 0.f;
        const float* bp = bs[b][fl];
        const float* aqc = aqs[c];
        const float* akc = aks[c];
#pragma unroll 8
        for (int u = 0; u < UU; ++u) {
            float bv = bp[u];
            dq += bv * aqc[u];
            dk += bv * akc[u];
        }
        float cb = coeff[c * BB + b];
        sq += cb * dq;
        sk += cb * dk;
    }
    int f = f_base + fl;
    g_wqk[f * 64 + c]      = sq;
    g_wqk[f * 64 + 32 + c] = sk;
}

// ---------------- K1: 128x64 FFMA2 GEMM (qk only) ----------------
#define GROWS 128
#define KC 128
#define XPAD 132
#define GEMM_SMEM ((KC * XPAD + KC * 64) * 4)

__global__ __launch_bounds__(256, 2) void k_gemm(const float* __restrict__ x,
                                                 const float* __restrict__ w,
                                                 float* __restrict__ out,
                                                 int ostride, int cmul, int cadd0,
                                                 int bstride, int caddstep) {
    extern __shared__ float sm[];
    float* xs = sm;
    float* ws = sm + KC * XPAD;
    int tid = threadIdx.x;
    int tx = tid & 15, ty = tid >> 4;
    int m0 = blockIdx.x * GROWS;
    const float* wb = w + (size_t)blockIdx.y * bstride;
    int cadd = cadd0 + blockIdx.y * caddstep;

    ull acc[4][4];
#pragma unroll
    for (int i = 0; i < 4; ++i)
#pragma unroll
        for (int j = 0; j < 4; ++j) acc[i][j] = 0ull;

    for (int kc = 0; kc < 2; ++kc) {
        if (kc) __syncthreads();
        const float4* w4 = (const float4*)(wb + kc * KC * 64);
        float4* ws4 = (float4*)ws;
        for (int i = tid; i < KC * 16; i += 256) ws4[i] = w4[i];
        const float4* x4 = (const float4*)x;
        for (int i = tid; i < GROWS * 32; i += 256) {
            int row = i >> 5, k4 = i & 31;
            int n = m0 + row;
            float4 v = make_float4(0.f, 0.f, 0.f, 0.f);
            if (n < NN) v = x4[n * 64 + kc * 32 + k4];
            xs[(k4 * 4 + 0) * XPAD + row] = v.x;
            xs[(k4 * 4 + 1) * XPAD + row] = v.y;
            xs[(k4 * 4 + 2) * XPAD + row] = v.z;
            xs[(k4 * 4 + 3) * XPAD + row] = v.w;
        }
        __syncthreads();

        const float* wp = ws + tx * 4;
        const float* xp = xs + ty * 8;
#pragma unroll 8
        for (int k = 0; k < KC; ++k) {
            float4 bv = *(const float4*)(wp + k * 64);
            const float* xr = xp + k * XPAD;
            ull a0 = *(const ull*)(xr);
            ull a1 = *(const ull*)(xr + 2);
            ull a2 = *(const ull*)(xr + 4);
            ull a3 = *(const ull*)(xr + 6);
            ull s0 = splat2(bv.x), s1 = splat2(bv.y),
                s2 = splat2(bv.z), s3 = splat2(bv.w);
            fma2(acc[0][0], a0, s0); fma2(acc[1][0], a1, s0);
            fma2(acc[2][0], a2, s0); fma2(acc[3][0], a3, s0);
            fma2(acc[0][1], a0, s1); fma2(acc[1][1], a1, s1);
            fma2(acc[2][1], a2, s1); fma2(acc[3][1], a3, s1);
            fma2(acc[0][2], a0, s2); fma2(acc[1][2], a1, s2);
            fma2(acc[2][2], a2, s2); fma2(acc[3][2], a3, s2);
            fma2(acc[0][3], a0, s3); fma2(acc[1][3], a1, s3);
            fma2(acc[2][3], a2, s3); fma2(acc[3][3], a3, s3);
        }
    }

    int col0 = tx * 4;
#pragma unroll
    for (int ip = 0; ip < 4; ++ip) {
        float lo[4], hi[4];
#pragma unroll
        for (int j = 0; j < 4; ++j) unpk2(lo[j], hi[j], acc[ip][j]);
        int n0 = m0 + ty * 8 + ip * 2;
        if (n0 < NN) {
            float* o = out + (size_t)n0 * ostride + cadd;
#pragma unroll
            for (int j = 0; j < 4; ++j) o[(col0 + j) * cmul] = lo[j];
        }
        if (n0 + 1 < NN) {
            float* o = out + (size_t)(n0 + 1) * ostride + cadd;
#pragma unroll
            for (int j = 0; j < 4; ++j) o[(col0 + j) * cmul] = hi[j];
        }
    }
}

// ---------------- counting sort ----------------
__global__ void k_hist(const int* __restrict__ dst) {
    int i = blockIdx.x * blockDim.x + threadIdx.x;
    if (i * 4 < EE) {
        int4 d4 = ((const int4*)dst)[i];
        atomicAdd(&g_deg[d4.x], 1);
        atomicAdd(&g_deg[d4.y], 1);
        atomicAdd(&g_deg[d4.z], 1);
        atomicAdd(&g_deg[d4.w], 1);
    }
}

__global__ __launch_bounds__(256) void k_scan() {
    int t = threadIdx.x, lane = t & 31, wid = t >> 5, bid = blockIdx.x;
    int i = bid * 256 + t;
    int v = (i < NN) ? g_deg[i] : 0;
    int inc = v;
#pragma unroll
    for (int o = 1; o < 32; o <<= 1) {
        int u = __shfl_up_sync(0xffffffffu, inc, o);
        if (lane >= o) inc += u;
    }
    __shared__ int ws[8], ws2[8], s_base;
    if (lane == 31) ws[wid] = inc;
    __syncthreads();
    if (t == 0) {
        int btot = 0;
#pragma unroll
        for (int w = 0; w < 8; ++w) btot += ws[w];
        atomicExch(&g_bsum[bid], -(btot + 1));
    }
    int part = 0;
    if (t < bid) {
        volatile int* vb = g_bsum;
        int sv;
        do { sv = vb[t]; } while (sv >= 0);
        part = -sv - 1;
    }
#pragma unroll
    for (int o = 16; o; o >>= 1) part += __shfl_xor_sync(0xffffffffu, part, o);
    if (lane == 0) ws2[wid] = part;
    __syncthreads();
    if (t == 0) {
        int b = 0;
#pragma unroll
        for (int w = 0; w < 8; ++w) b += ws2[w];
        s_base = b;
    }
    __syncthreads();
    int wpre = 0;
#pragma unroll
    for (int w = 0; w < 8; ++w) wpre += (w < wid) ? ws[w] : 0;
    int excl = s_base + wpre + inc - v;
    if (i < NN) { g_off[i] = excl; g_cur[i] = excl; g_deg[i] = 0; }
    if (bid == NBLK - 1 && t == 255) g_off[NN] = EE;
}

__global__ void k_scatter(const int* __restrict__ src,
                          const int* __restrict__ dst,
                          const int* __restrict__ rel) {
    int j = blockIdx.x * blockDim.x + threadIdx.x;
    if (j < EE / 4) {
        int4 s4 = ((const int4*)src)[j];
        int4 d4 = ((const int4*)dst)[j];
        int4 r4 = ((const int4*)rel)[j];
        int p;
        p = atomicAdd(&g_cur[d4.x], 1); g_packed[p] = s4.x | (r4.x << 16);
        p = atomicAdd(&g_cur[d4.y], 1); g_packed[p] = s4.y | (r4.y << 16);
        p = atomicAdd(&g_cur[d4.z], 1); g_packed[p] = s4.z | (r4.z << 16);
        p = atomicAdd(&g_cur[d4.w], 1); g_packed[p] = s4.w | (r4.w << 16);
    }
    if (blockIdx.x == 0 && threadIdx.x < NBLK) g_bsum[threadIdx.x] = 0;
}

// ---------------- per-node: logits + softmax + head-folded beta ----------
__global__ __launch_bounds__(256) void k_mxden(const float* __restrict__ coeff) {
    __shared__ __align__(16) float cf[CC * BB];
    int tid = threadIdx.x;
    if (tid < CC * BB) cf[tid] = coeff[tid];
    __syncthreads();

    int lane = tid & 31, w = tid >> 5;
    int n = blockIdx.x * 8 + w;
    if (n >= NN) return;
    int beg = g_off[n], end = g_off[n + 1];
    if (beg == end) return;

    float kv = g_qk[n * 64 + 32 + lane];
    int h = lane & 3;
    float* lg = (float*)g_alpha;

    float mx = __int_as_float(0xff800000);
    for (int e0 = beg; e0 < end; e0 += 8) {
        int e = e0 + (lane >> 2);
        bool valid = (e < end);
        int pk = g_packed[valid ? e : beg];
        int s = pk & 0xFFFF, r = pk >> 16;
        float q = valid ? g_qk[s * 64 + r * 4 + h] : 0.f;
        float kk = __shfl_sync(0xffffffffu, kv, r * 4 + h);
        float l = q + kk;
        l = l > 0.f ? l : 0.01f * l;
        if (valid) {
            lg[e0 * 4 + lane] = l;
            mx = fmaxf(mx, l);
        }
    }
    mx = fmaxf(mx, __shfl_xor_sync(0xffffffffu, mx, 4));
    mx = fmaxf(mx, __shfl_xor_sync(0xffffffffu, mx, 8));
    mx = fmaxf(mx, __shfl_xor_sync(0xffffffffu, mx, 16));

    float dsum = 0.f;
    for (int e0 = beg; e0 < end; e0 += 8) {
        int idx = e0 * 4 + lane;
        if (idx < end * 4) {
            float wv = __expf(lg[idx] - mx);
            lg[idx] = wv;
            dsum += wv;
        }
    }
    dsum += __shfl_xor_sync(0xffffffffu, dsum, 4);
    dsum += __shfl_xor_sync(0xffffffffu, dsum, 8);
    dsum += __shfl_xor_sync(0xffffffffu, dsum, 16);
    float inv_self = 1.f / fmaxf(dsum, 1e-16f);
    float inv0 = __shfl_sync(0xffffffffu, inv_self, 0);
    float inv1 = __shfl_sync(0xffffffffu, inv_self, 1);
    float inv2 = __shfl_sync(0xffffffffu, inv_self, 2);
    float inv3 = __shfl_sync(0xffffffffu, inv_self, 3);

    float* bt = (float*)g_beta;
    for (int e0 = beg; e0 < end; e0 += 8) {
        int idx = e0 * 4 + lane;
        if (idx < end * 4) {
            int e = idx >> 2, b = idx & 3;
            int r = g_packed[e] >> 16;
            float w0 = lg[e * 4 + 0];
            float w1 = lg[e * 4 + 1];
            float w2 = lg[e * 4 + 2];
            float w3 = lg[e * 4 + 3];
            const float* cr = cf + r * 16;
            float bv = inv0 * w0 * cr[b]
                     + inv1 * w1 * cr[4 + b]
                     + inv2 * w2 * cr[8 + b]
                     + inv3 * w3 * cr[12 + b];
            bt[idx] = bv;
        }
    }
}

// ---------------- aggregation (validated best) ----------------
__global__ __launch_bounds__(256) void k_agg(float* __restrict__ out) {
    __shared__ float s_part[4][64];
    int tid = threadIdx.x;
    int lane = tid & 31, w = tid >> 5;
    int node = w >> 1;
    int sub = w & 1;
    int n = blockIdx.x * 4 + node;
    bool active = (n < NN);

    int beg = 0, end = 0;
    if (active) { beg = g_off[n]; end = g_off[n + 1]; }
    int len = end - beg;
    int half = (len + 1) >> 1;
    int mybeg = beg + (sub ? half : 0);
    int myend = sub ? end : (beg + half);

    ull acc00 = 0ull, acc01 = 0ull, acc10 = 0ull, acc11 = 0ull;

    if (mybeg < myend) {
        int pk = g_packed[mybeg];
        for (int e = mybeg; e < myend; ++e) {
            int pkc = pk;
            if (e + 1 < myend) pk = g_packed[e + 1];

            int s = pkc & 0xFFFF;
            float4 bt = g_beta[e];
            const float4* yr = (const float4*)(g_y + (size_t)s * 256);
            float4 y0 = yr[lane];
            float4 y1 = yr[32 + lane];
            ull b01 = pack2(bt.x, bt.y);
            ull b23 = pack2(bt.z, bt.w);
            fma2(acc00, b01, pack2(y0.x, y0.y));
            fma2(acc01, b23, pack2(y0.z, y0.w));
            fma2(acc10, b01, pack2(y1.x, y1.y));
            fma2(acc11, b23, pack2(y1.z, y1.w));
        }
    }

    float o0, o1;
    {
        float l0, h0, l1, h1, l2, h2, l3, h3;
        unpk2(l0, h0, acc00);
        unpk2(l1, h1, acc01);
        unpk2(l2, h2, acc10);
        unpk2(l3, h3, acc11);
        o0 = (l0 + h0) + (l1 + h1);
        o1 = (l2 + h2) + (l3 + h3);
    }

    if (sub == 1) {
        s_part[node][lane] = o0;
        s_part[node][32 + lane] = o1;
    }
    __syncthreads();

    if (sub == 0 && active) {
        o0 += s_part[node][lane];
        o1 += s_part[node][32 + lane];
        out[n * UU + lane] = 0.25f * o0;
        out[n * UU + 32 + lane] = 0.25f * o1;
    }
}

// ---------------- launch ----------------
extern "C" void kernel_launch(void* const* d_in, const int* in_sizes, int n_in,
                              void* d_out, int out_size) {
    const float* x     = (const float*)d_in[0];
    const float* basis = (const float*)d_in[1];
    const float* coeff = (const float*)d_in[2];
    const float* aq    = (const float*)d_in[3];
    const float* ak    = (const float*)d_in[4];
    const int*   src   = (const int*)d_in[5];
    const int*   dst   = (const int*)d_in[6];
    const int*   rel   = (const int*)d_in[7];
    float* out = (float*)d_out;

    float* d_qk;  cudaGetSymbolAddress((void**)&d_qk, g_qk);
    float* d_wqk; cudaGetSymbolAddress((void**)&d_wqk, g_wqk);

    cudaFuncSetAttribute(k_gemm, cudaFuncAttributeMaxDynamicSharedMemorySize, GEMM_SMEM);
    cudaFuncSetAttribute(k_yhmma, cudaFuncAttributeMaxDynamicSharedMemorySize, YH_SMEM);

    cudaStream_t s1 = 0, s2 = 0;
    bool fork = s_forkOK;
    if (fork) {
        s1 = s_s1; s2 = s_s2;
        cudaEventRecord(s_evRoot, 0);
        cudaStreamWaitEvent(s1, s_evRoot, 0);
        cudaStreamWaitEvent(s2, s_evRoot, 0);
    }

    // --- side stream 1: prep -> qk GEMM ---
    k_prep<<<32, 256, 0, s1>>>(coeff, basis, aq, ak);
    k_gemm<<<dim3((NN + GROWS - 1) / GROWS, 1), 256, GEMM_SMEM, s1>>>(
        x, d_wqk, d_qk, 64, 1, 0, 0, 0);

    // --- side stream 2: W tf32 split -> HMMA y GEMM ---
    k_cvtw<<<(BB * FF * UU + 255) / 256, 256, 0, s2>>>(basis);
    k_yhmma<<<dim3((NN + 127) / 128, BB), 256, YH_SMEM, s2>>>(x);

    if (fork) {
        cudaEventRecord(s_evA, s1);
        cudaEventRecord(s_evB, s2);
    }

    // --- main stream: counting sort ---
    k_hist<<<(EE / 4 + 255) / 256, 256>>>(dst);
    k_scan<<<NBLK, 256>>>();
    k_scatter<<<(EE / 4 + 255) / 256, 256>>>(src, dst, rel);

    // mxden reads g_qk -> wait for qk GEMM
    if (fork) cudaStreamWaitEvent(0, s_evA, 0);
    k_mxden<<<(NN + 7) / 8, 256>>>(coeff);

    if (fork) cudaStreamWaitEvent(0, s_evB, 0);
    k_agg<<<(NN + 3) / 4, 256>>>(out);
}